// round 13
// baseline (speedup 1.0000x reference)
#include <cuda_runtime.h>
#include <cuda_fp16.h>
#include <math.h>
#include <stdint.h>

#define NB    16
#define CIN   256
#define HW    1024
#define INNER 512
#define CTXN  77
#define CTXD  768
#define DH    64

// ===================== PTX helpers (sm_80-safe only) =========================
__device__ __forceinline__ uint32_t smem_to_u32(const void* p) {
    uint32_t a;
    asm("{ .reg .u64 t; cvta.to.shared.u64 t, %1; cvt.u32.u64 %0, t; }" : "=r"(a) : "l"(p));
    return a;
}
__device__ __forceinline__ void cp16(uint32_t dst, const void* src, bool valid) {
    int sz = valid ? 16 : 0;
    asm volatile("cp.async.cg.shared.global [%0], [%1], 16, %2;"
                 :: "r"(dst), "l"(src), "r"(sz) : "memory");
}
#define CP_COMMIT() asm volatile("cp.async.commit_group;" ::: "memory")
template <int N>
__device__ __forceinline__ void cp_wait() {
    asm volatile("cp.async.wait_group %0;" :: "n"(N) : "memory");
}
__device__ __forceinline__ void ldsm_x4(uint32_t* r, uint32_t addr) {
    asm volatile("ldmatrix.sync.aligned.m8n8.x4.shared.b16 {%0,%1,%2,%3}, [%4];"
        : "=r"(r[0]), "=r"(r[1]), "=r"(r[2]), "=r"(r[3]) : "r"(addr));
}
__device__ __forceinline__ void mma_f16(float* d, const uint32_t* a,
                                        uint32_t b0, uint32_t b1) {
    asm volatile(
        "mma.sync.aligned.m16n8k16.row.col.f32.f16.f16.f32 "
        "{%0,%1,%2,%3}, {%4,%5,%6,%7}, {%8,%9}, {%0,%1,%2,%3};"
        : "+f"(d[0]), "+f"(d[1]), "+f"(d[2]), "+f"(d[3])
        : "r"(a[0]), "r"(a[1]), "r"(a[2]), "r"(a[3]), "r"(b0), "r"(b1));
}

// ===================== scratch (device globals) ==============================
#define WH_TOTAL 3567616L
__device__ __align__(16) __half g_wh[WH_TOTAL];            // fp16 weights + ctx
__device__ __align__(16) float g_h0 [NB * HW * INNER];     // conv_in out (fp32)
__device__ __align__(16) float g_h1 [NB * HW * INNER];     // after SA (fp32)
__device__ __align__(16) float g_kvc[NB * CTXN * 1024];
__device__ __align__(16) float g_rsum[NB * HW];            // softmax row sums
__device__ __align__(16) float g_gst[NB * 32 * 2];         // GN2 group s/ss
__device__ float g_stats[NB * 32 * 2];
__device__ __align__(16) __half g_xnh [NB * HW * CIN];
__device__ __align__(16) __half g_hnh [NB * HW * INNER];
__device__ __align__(16) __half g_qkh [NB * HW * 1024];    // q|k merged
__device__ __align__(16) __half g_qh  [NB * HW * INNER];   // CA q
__device__ __align__(16) __half g_vth [NB * HW * INNER];   // v^T
__device__ __align__(16) __half g_oh  [NB * HW * INNER];   // SA attn out
__device__ __align__(16) __half g_h1h [NB * HW * INNER];
__device__ __align__(16) __half g_h2h [NB * HW * INNER];
__device__ __align__(16) __half g_ofh [NB * HW * INNER];   // CA attn out
__device__ __align__(16) __half g_attn[(long)NB * HW * HW];

// ===================== reductions ============================================
__device__ __forceinline__ float warpSum(float v) {
#pragma unroll
    for (int o = 16; o; o >>= 1) v += __shfl_xor_sync(0xffffffffu, v, o);
    return v;
}
__device__ float blockSum(float v) {
    __shared__ float sm[8];
    int t = threadIdx.x;
    v = warpSum(v);
    if ((t & 31) == 0) sm[t >> 5] = v;
    __syncthreads();
    if (t < 32) {
        float w = (t < 8) ? sm[t] : 0.f;
        w = warpSum(w);
        if (t == 0) sm[0] = w;
    }
    __syncthreads();
    float r = sm[0];
    __syncthreads();
    return r;
}

// ===================== conversions ===========================================
struct CvtSrc { const float* p[11]; };
__global__ void cvt_k(CvtSrc a) {
    long i = (long)blockIdx.x * 256 + threadIdx.x;
    if (i >= WH_TOTAL) return;
    const long ends[11] = {131072, 393216, 655360, 917504, 1179648, 1441792,
                           1835008, 2228224, 2490368, 2621440, 3567616};
    int s = 0; long off = 0;
#pragma unroll
    for (int k = 0; k < 11; k++) {
        if (i >= ends[k]) { s = k + 1; off = ends[k]; }
    }
    g_wh[i] = __float2half_rn(a.p[s][i - off]);
}

// ===================== GroupNorm 1 ===========================================
__global__ void gn1_stats_k(const float* __restrict__ x) {
    int bg = blockIdx.x;
    // zero per-replay accumulators (this kernel runs first)
    if (threadIdx.x < 32) g_rsum[bg * 32 + threadIdx.x] = 0.f;
    if (threadIdx.x < 2)  g_gst[bg * 2 + threadIdx.x] = 0.f;
    const float* p = x + (long)bg * 8192;
    float s = 0.f, ss = 0.f;
    for (int i = threadIdx.x; i < 2048; i += 256) {
        float4 v = ((const float4*)p)[i];
        s += v.x + v.y + v.z + v.w;
        ss += v.x * v.x + v.y * v.y + v.z * v.z + v.w * v.w;
    }
    s = blockSum(s); ss = blockSum(ss);
    if (threadIdx.x == 0) {
        float mean = s * (1.f / 8192.f);
        float var  = ss * (1.f / 8192.f) - mean * mean;
        g_stats[bg * 2]     = mean;
        g_stats[bg * 2 + 1] = rsqrtf(var + 1e-5f);
    }
}
// tiled transpose + normalize: x [b][c][n] fp32 -> xnh [b][n][c] fp16
__global__ void gn1_apply_k(const float* __restrict__ x,
                            const float* __restrict__ gam,
                            const float* __restrict__ bet) {
    __shared__ float t[32][33];
    int b = blockIdx.z;
    int c0 = blockIdx.y * 32;
    int n0 = blockIdx.x * 32;
    int tx = threadIdx.x, ty = threadIdx.y;
#pragma unroll
    for (int i = 0; i < 4; i++) {
        int c = c0 + ty + i * 8;
        float v = x[((long)(b * 256 + c) << 10) + n0 + tx];
        int sg = (b << 5) | (c >> 3);
        t[ty + i * 8][tx] = (v - g_stats[sg * 2]) * g_stats[sg * 2 + 1] * gam[c] + bet[c];
    }
    __syncthreads();
#pragma unroll
    for (int i = 0; i < 4; i++) {
        int n = n0 + ty + i * 8;
        g_xnh[((long)(b * 1024 + n) << 8) + c0 + tx] = __float2half_rn(t[tx][ty + i * 8]);
    }
}

// ===================== GroupNorm 2 apply (stats fused into conv_in) ==========
__global__ void gn2_apply_k(const float* __restrict__ gg,
                            const float* __restrict__ gb) {
    int b = blockIdx.x >> 5, g = blockIdx.x & 31;
    float s  = g_gst[(b * 32 + g) * 2];
    float ss = g_gst[(b * 32 + g) * 2 + 1];
    float mean = s * (1.f / 16384.f);
    float rstd = rsqrtf(ss * (1.f / 16384.f) - mean * mean + 1e-5f);
    const float4* p = (const float4*)(g_h0 + (long)b * HW * INNER + g * 16);
    __half* q = g_hnh + (long)b * HW * INNER + g * 16;
    for (int i = threadIdx.x; i < HW * 4; i += 256) {
        int n = i >> 2, j = i & 3;
        int c = g * 16 + j * 4;
        float4 v = p[n * 128 + j];
        __half2 h0 = __floats2half2_rn(
            (v.x - mean) * rstd * gg[c] + gb[c],
            (v.y - mean) * rstd * gg[c + 1] + gb[c + 1]);
        __half2 h1 = __floats2half2_rn(
            (v.z - mean) * rstd * gg[c + 2] + gb[c + 2],
            (v.w - mean) * rstd * gg[c + 3] + gb[c + 3]);
        *(uint2*)(q + n * INNER + j * 4) = make_uint2(
            *(uint32_t*)&h0, *(uint32_t*)&h1);
    }
}

// ===================== fused cross-attention (half2 math) ====================
__global__ void __launch_bounds__(256) ca_attn_k() {
    __shared__ __half2 Ks[CTXN][DH / 2];
    __shared__ __half2 Vs[CTXN][DH / 2];
    int b = blockIdx.x >> 3, h = blockIdx.x & 7;
    const float2* kp = (const float2*)(g_kvc + (long)b * CTXN * 1024 + h * DH);
    const float2* vp = (const float2*)(g_kvc + (long)b * CTXN * 1024 + 512 + h * DH);
    for (int i = threadIdx.x; i < CTXN * 32; i += 256) {
        int j = i >> 5, d = i & 31;
        float2 kf = kp[j * 512 + d];
        float2 vf = vp[j * 512 + d];
        Ks[j][d] = __floats2half2_rn(kf.x, kf.y);
        Vs[j][d] = __floats2half2_rn(vf.x, vf.y);
    }
    __syncthreads();
    int i = blockIdx.y * 256 + threadIdx.x;
    const __half2* qp = (const __half2*)(g_qh + ((long)(b * HW + i)) * INNER + h * DH);
    __half2 qv[32];
    uint4* qv4 = (uint4*)qv;
#pragma unroll
    for (int d = 0; d < 8; d++) qv4[d] = ((const uint4*)qp)[d];

    float l = 0.f;
    __half2 acc[32];
    const __half2 z2 = __float2half2_rn(0.f);
#pragma unroll
    for (int d = 0; d < 32; d++) acc[d] = z2;
    for (int j = 0; j < CTXN; j++) {
        __half2 d2 = __hmul2(qv[0], Ks[j][0]);
#pragma unroll
        for (int d = 1; d < 32; d++) d2 = __hfma2(qv[d], Ks[j][d], d2);
        float s = (__low2float(d2) + __high2float(d2)) * 0.125f;
        float e = __expf(s);
        l += e;
        __half2 e2 = __float2half2_rn(e);
#pragma unroll
        for (int d = 0; d < 32; d++) acc[d] = __hfma2(e2, Vs[j][d], acc[d]);
    }
    float inv = 1.f / l;
    __half* op = g_ofh + ((long)(b * HW + i)) * INNER + h * DH;
#pragma unroll
    for (int d = 0; d < 32; d += 4) {
        __half2 pk[4];
#pragma unroll
        for (int e = 0; e < 4; e++) {
            float2 a = __half22float2(acc[d + e]);
            pk[e] = __floats2half2_rn(a.x * inv, a.y * inv);
        }
        *(uint4*)(op + d * 2) = *(uint4*)pk;
    }
}

// ===================== fp16 mma.sync GEMM (unified modes) ====================
// mode 0: C row-major (stride ldc); optional rsum (exp+rowsum), rdiv
//         (1/rowsum scale), gstats (GN2 group stats), bias, R residual.
// mode 1: C transposed [N, M] per batch (staged, coalesced), Cf/Cb.
// mode 2: merged qkv — bn<1024: store Cb (qkh, ldc); bn>=1024: store Cb2
//         (v^T at [vrow=bn-1024+nl][m], per-batch 512x1024), staged.
// CTA 128x128, 8 warps (2x4, 64x32), BK=64, 3 stages x 32KB, 2 CTAs/SM.
#define STAGE_B 32768
#define GSMEM   98304

__device__ __forceinline__ void frag_load(
    uint32_t aT, uint32_t bT, int wm, int wn, int lane, int kk,
    uint32_t af[4][4], uint32_t bfr[2][4]) {
    const int r0 = lane & 15;
    const int uu = kk * 2 + (lane >> 4);
#pragma unroll
    for (int mi = 0; mi < 4; mi++) {
        int r = wm + mi * 16 + r0;
        ldsm_x4(af[mi], aT + r * 128 + ((uu ^ (r & 7)) << 4));
    }
#pragma unroll
    for (int p = 0; p < 2; p++) {
        int r = wn + p * 16 + r0;
        ldsm_x4(bfr[p], bT + r * 128 + ((uu ^ (r & 7)) << 4));
    }
}

__global__ void __launch_bounds__(256, 2) gemm_mma(
    const __half* __restrict__ A_, long sA, int lda,
    const __half* __restrict__ B_, long sB, int ldb,
    float* __restrict__ Cf, __half* __restrict__ Cb, __half* __restrict__ Cb2,
    const float* __restrict__ bias, const float* __restrict__ R,
    float rcoef, float alpha, int M, int N, int K, int ldc, int mode,
    float* __restrict__ rsum, const float* __restrict__ rdiv,
    float* __restrict__ gstats) {
    extern __shared__ __align__(128) char sm[];
    const uint32_t sb = smem_to_u32(sm);
    const int tid  = threadIdx.x;
    const int lane = tid & 31;
    const int wid  = tid >> 5;
    const int bz = blockIdx.z;
    const int bm = blockIdx.y * 128;
    const int bn = blockIdx.x * 128;
    const int wm = (wid >> 2) * 64;
    const int wn = (wid & 3) * 32;
    const __half* Ab = A_ + (long)bz * sA;
    const __half* Bb = B_ + (long)bz * sB;

    float acc[4][4][4];
#pragma unroll
    for (int i = 0; i < 4; i++)
#pragma unroll
        for (int j = 0; j < 4; j++)
#pragma unroll
            for (int e = 0; e < 4; e++) acc[i][j][e] = 0.f;

    const int lrow = tid >> 1;
    const int lu0  = (tid & 1) * 4;
    const bool aValid = (bm + lrow) < M;
    const long aOff = aValid ? (long)(bm + lrow) * lda : 0;
    const long bOff = (long)(bn + lrow) * ldb;
    const int nIter = K >> 6;

#define LOADC(i, s) do {                                                        \
    uint32_t dA = sb + (s) * STAGE_B + lrow * 128;                              \
    uint32_t dB = dA + 16384;                                                   \
    const __half* gA = Ab + aOff + ((long)(i) << 6);                            \
    const __half* gB = Bb + bOff + ((long)(i) << 6);                            \
    _Pragma("unroll")                                                           \
    for (int j = 0; j < 4; j++) {                                               \
        int u = lu0 + j;                                                        \
        uint32_t so = (uint32_t)((u ^ (lrow & 7)) << 4);                        \
        cp16(dA + so, gA + u * 8, aValid);                                      \
        cp16(dB + so, gB + u * 8, true);                                        \
    }                                                                           \
} while (0)

    LOADC(0, 0); CP_COMMIT();
    if (1 < nIter) { LOADC(1, 1); }
    CP_COMMIT();

    uint32_t af[4][4], bfr[2][4];

    for (int it = 0; it < nIter; it++) {
        const int s = it % 3;
        if (it + 1 < nIter) cp_wait<1>(); else cp_wait<0>();
        __syncthreads();
        if (it + 2 < nIter) { LOADC(it + 2, (it + 2) % 3); CP_COMMIT(); }

        const uint32_t aT = sb + s * STAGE_B;
        const uint32_t bT = aT + 16384;
#pragma unroll
        for (int kk = 0; kk < 4; kk++) {
            frag_load(aT, bT, wm, wn, lane, kk, af, bfr);
#pragma unroll
            for (int mi = 0; mi < 4; mi++)
#pragma unroll
                for (int p = 0; p < 2; p++) {
                    mma_f16(acc[mi][2 * p],     af[mi], bfr[p][0], bfr[p][2]);
                    mma_f16(acc[mi][2 * p + 1], af[mi], bfr[p][1], bfr[p][3]);
                }
        }
        __syncthreads();
    }

    // ------------------------------ epilogue ------------------------------
    const int tr = lane >> 2;
    const int tc = (lane & 3) * 2;
    const bool staged = (mode == 1) || (mode == 2 && bn >= 1024);
    if (staged) {
        float* st = (float*)sm;
#pragma unroll
        for (int mi = 0; mi < 4; mi++)
#pragma unroll
            for (int r2 = 0; r2 < 2; r2++) {
                const int ml = wm + mi * 16 + tr + r2 * 8;
#pragma unroll
                for (int nj = 0; nj < 4; nj++) {
                    const int nl = wn + nj * 8 + tc;
                    st[nl * 132 + ml]       = acc[mi][nj][r2 * 2 + 0] * alpha;
                    st[(nl + 1) * 132 + ml] = acc[mi][nj][r2 * 2 + 1] * alpha;
                }
            }
        __syncthreads();
        if (mode == 1) {
            const long bzMN = (long)bz * M * N;
#pragma unroll
            for (int r = 0; r < 16; r++) {
                const int nl = wid * 16 + r;
                const int n = bn + nl;
                float bv = bias ? bias[n] : 0.f;
                float4 v = *(float4*)&st[nl * 132 + lane * 4];
                v.x += bv; v.y += bv; v.z += bv; v.w += bv;
                const long i0 = bzMN + (long)n * M + bm + lane * 4;
                if (R) {
                    float4 rv = *(const float4*)(R + i0);
                    v.x += rcoef * rv.x; v.y += rcoef * rv.y;
                    v.z += rcoef * rv.z; v.w += rcoef * rv.w;
                }
                if (Cf) *(float4*)(Cf + i0) = v;
                if (Cb) {
                    __half2 h0v = __floats2half2_rn(v.x, v.y);
                    __half2 h1v = __floats2half2_rn(v.z, v.w);
                    *(uint2*)(Cb + i0) = make_uint2(*(uint32_t*)&h0v, *(uint32_t*)&h1v);
                }
            }
        } else {
            // mode 2 v-part: write half tile transposed into Cb2 (v^T)
#pragma unroll
            for (int r = 0; r < 16; r++) {
                const int nl = wid * 16 + r;
                const int vrow = bn - 1024 + nl;
                float4 v = *(float4*)&st[nl * 132 + lane * 4];
                __half2 h0v = __floats2half2_rn(v.x, v.y);
                __half2 h1v = __floats2half2_rn(v.z, v.w);
                const long i0 = (long)bz * 524288 + (long)vrow * 1024 + bm + lane * 4;
                *(uint2*)(Cb2 + i0) = make_uint2(*(uint32_t*)&h0v, *(uint32_t*)&h1v);
            }
        }
    } else {
        const long bzC = (long)bz * M * ldc;
        float gs0 = 0.f, gss0 = 0.f, gs1 = 0.f, gss1 = 0.f;
#pragma unroll
        for (int mi = 0; mi < 4; mi++) {
#pragma unroll
            for (int r2 = 0; r2 < 2; r2++) {
                const int m = bm + wm + mi * 16 + tr + r2 * 8;
                if (m >= M) continue;
                float rAcc = 0.f;
                float inv = 1.f;
                if (rdiv) inv = 1.f / rdiv[(long)bz * M + m];
#pragma unroll
                for (int nj = 0; nj < 4; nj++) {
                    const int n = bn + wn + nj * 8 + tc;
                    float v0 = acc[mi][nj][r2 * 2 + 0] * alpha;
                    float v1 = acc[mi][nj][r2 * 2 + 1] * alpha;
                    if (bias) { v0 += bias[n]; v1 += bias[n + 1]; }
                    if (rsum) {
                        v0 = __expf(v0); v1 = __expf(v1);
                        rAcc += v0 + v1;
                    }
                    v0 *= inv; v1 *= inv;
                    const long i0 = bzC + (long)m * ldc + n;
                    if (R) {
                        float2 rv = *(const float2*)(R + i0);
                        v0 += rcoef * rv.x; v1 += rcoef * rv.y;
                    }
                    if (gstats) {
                        if (nj < 2) { gs0 += v0 + v1; gss0 += v0 * v0 + v1 * v1; }
                        else        { gs1 += v0 + v1; gss1 += v0 * v0 + v1 * v1; }
                    }
                    if (Cf) *(float2*)(Cf + i0) = make_float2(v0, v1);
                    if (Cb) {
                        __half2 hv = __floats2half2_rn(v0, v1);
                        *(uint32_t*)(Cb + i0) = *(uint32_t*)&hv;
                    }
                }
                if (rsum) {
                    rAcc += __shfl_xor_sync(0xffffffffu, rAcc, 1);
                    rAcc += __shfl_xor_sync(0xffffffffu, rAcc, 2);
                    if ((lane & 3) == 0)
                        atomicAdd(&rsum[(long)bz * M + m], rAcc);
                }
            }
        }
        if (gstats) {
            const int g0 = (bn + wn) >> 4;
            atomicAdd(&gstats[((long)bz * 32 + g0) * 2],     gs0);
            atomicAdd(&gstats[((long)bz * 32 + g0) * 2 + 1], gss0);
            atomicAdd(&gstats[((long)bz * 32 + g0 + 1) * 2],     gs1);
            atomicAdd(&gstats[((long)bz * 32 + g0 + 1) * 2 + 1], gss1);
        }
    }
#undef LOADC
}

static void gemm(const __half* A, long sA, int lda,
                 const __half* B, long sB, int ldb,
                 float* Cf, __half* Cb, __half* Cb2,
                 const float* bias, const float* R,
                 float rcoef, float alpha, int M, int N, int K, int ldc, int mode,
                 float* rsum, const float* rdiv, float* gstats) {
    static int s_attr = 0;
    if (!s_attr) {
        cudaFuncSetAttribute(gemm_mma, cudaFuncAttributeMaxDynamicSharedMemorySize, GSMEM);
        s_attr = 1;
    }
    dim3 grid(N / 128, (M + 127) / 128, NB);
    gemm_mma<<<grid, 256, GSMEM>>>(A, sA, lda, B, sB, ldb, Cf, Cb, Cb2,
                                   bias, R, rcoef, alpha, M, N, K, ldc, mode,
                                   rsum, rdiv, gstats);
}

// ===================== driver ================================================
extern "C" void kernel_launch(void* const* d_in, const int* in_sizes, int n_in,
                              void* d_out, int out_size) {
    const float* x      = (const float*)d_in[0];
    const float* ctx    = (const float*)d_in[1];
    const float* gn1_g  = (const float*)d_in[2];
    const float* gn1_b  = (const float*)d_in[3];
    const float* w_in   = (const float*)d_in[4];
    const float* b_in   = (const float*)d_in[5];
    const float* sa_wk  = (const float*)d_in[6];
    const float* sa_wq  = (const float*)d_in[7];
    const float* sa_wv  = (const float*)d_in[8];
    const float* sa_wp  = (const float*)d_in[9];
    const float* sa_gng = (const float*)d_in[10];
    const float* sa_gnb = (const float*)d_in[11];
    const float* ca_wq  = (const float*)d_in[12];
    const float* ca_wk  = (const float*)d_in[13];
    const float* ca_wv  = (const float*)d_in[14];
    const float* ca_wo  = (const float*)d_in[15];
    const float* ca_bo  = (const float*)d_in[16];
    const float* w_out  = (const float*)d_in[17];
    const float* b_out  = (const float*)d_in[18];
    float* out = (float*)d_out;

    float *h0, *h1, *kvc, *rs, *gst;
    __half *wh, *xnh, *hnh, *qkh, *qh, *vth, *oh, *h1h, *h2h, *ofh, *attnh;
    cudaGetSymbolAddress((void**)&h0,  g_h0);
    cudaGetSymbolAddress((void**)&h1,  g_h1);
    cudaGetSymbolAddress((void**)&kvc, g_kvc);
    cudaGetSymbolAddress((void**)&rs,  g_rsum);
    cudaGetSymbolAddress((void**)&gst, g_gst);
    cudaGetSymbolAddress((void**)&wh,  g_wh);
    cudaGetSymbolAddress((void**)&xnh, g_xnh);
    cudaGetSymbolAddress((void**)&hnh, g_hnh);
    cudaGetSymbolAddress((void**)&qkh, g_qkh);
    cudaGetSymbolAddress((void**)&qh,  g_qh);
    cudaGetSymbolAddress((void**)&vth, g_vth);
    cudaGetSymbolAddress((void**)&oh,  g_oh);
    cudaGetSymbolAddress((void**)&h1h, g_h1h);
    cudaGetSymbolAddress((void**)&h2h, g_h2h);
    cudaGetSymbolAddress((void**)&ofh, g_ofh);
    cudaGetSymbolAddress((void**)&attnh, g_attn);

    __half* wh_in   = wh;
    __half* wh_qkv  = wh + 131072;     // sa_wq | sa_wk | sa_wv contiguous [1536,512]
    __half* wh_sap  = wh + 917504;
    __half* wh_caq  = wh + 1179648;
    __half* wh_cakv = wh + 1441792;    // ca_wk | ca_wv [1024,768]
    __half* wh_cao  = wh + 2228224;
    __half* wh_out  = wh + 2490368;
    __half* ctx_h   = wh + 2621440;

    const float inv_sqrt_c = 0.044194173824159216f;   // 512^-0.5

    // 0. convert weights + ctx to fp16
    CvtSrc cs;
    cs.p[0] = w_in;  cs.p[1] = sa_wq; cs.p[2] = sa_wk; cs.p[3] = sa_wv;
    cs.p[4] = sa_wp; cs.p[5] = ca_wq; cs.p[6] = ca_wk; cs.p[7] = ca_wv;
    cs.p[8] = ca_wo; cs.p[9] = w_out; cs.p[10] = ctx;
    cvt_k<<<(int)((WH_TOTAL + 255) / 256), 256>>>(cs);

    // 1. GN1(x) -> xnh fp16 [b,n,c] (also zeroes rsum + gn2 stats)
    gn1_stats_k<<<NB * 32, 256>>>(x);
    gn1_apply_k<<<dim3(32, 8, NB), dim3(32, 8)>>>(x, gn1_g, gn1_b);
    // 2. conv_in: h0 = xn @ w_in^T + b_in (fp32); GN2 stats fused via atomics
    gemm(xnh, (long)HW * CIN, CIN, wh_in, 0, CIN, h0, nullptr, nullptr,
         b_in, nullptr, 0.f, 1.f, HW, INNER, CIN, INNER, 0, nullptr, nullptr, gst);
    // 3. GN2 apply only (single pass)
    gn2_apply_k<<<NB * 32, 256>>>(sa_gng, sa_gnb);
    // 4. merged q|k|v: N=1536; q|k -> qkh, v -> vth transposed (mode 2)
    gemm(hnh, (long)HW * INNER, INNER, wh_qkv, 0, INNER, nullptr, qkh, vth,
         nullptr, nullptr, 0.f, 1.f, HW, 1536, INNER, 1024, 2, nullptr, nullptr, nullptr);
    // 5. attn_unnorm = exp(q @ k^T * c^-0.5); rowsums accumulated
    gemm(qkh, (long)HW * 1024, 1024, qkh + 512, (long)HW * 1024, 1024,
         nullptr, attnh, nullptr, nullptr, nullptr, 0.f, inv_sqrt_c,
         HW, HW, INNER, HW, 0, rs, nullptr, nullptr);
    // 6. o = (exp_attn @ v) / rowsum -> oh fp16
    gemm(attnh, (long)HW * HW, HW, vth, (long)INNER * HW, HW,
         nullptr, oh, nullptr, nullptr, nullptr, 0.f, 1.f,
         HW, INNER, HW, INNER, 0, nullptr, rs, nullptr);
    // 7. h1 = o @ wp^T + 2*h0 (fp32 + fp16 copies)
    gemm(oh, (long)HW * INNER, INNER, wh_sap, 0, INNER, h1, h1h, nullptr,
         nullptr, h0, 2.f, 1.f, HW, INNER, INNER, INNER, 0, nullptr, nullptr, nullptr);
    // 8. CA projections: q fp16, fused k|v fp32
    gemm(h1h, (long)HW * INNER, INNER, wh_caq, 0, INNER, nullptr, qh, nullptr,
         nullptr, nullptr, 0.f, 1.f, HW, INNER, INNER, INNER, 0, nullptr, nullptr, nullptr);
    gemm(ctx_h, (long)CTXN * CTXD, CTXD, wh_cakv, 0, CTXD, kvc, nullptr, nullptr,
         nullptr, nullptr, 0.f, 1.f, CTXN, 1024, CTXD, 1024, 0, nullptr, nullptr, nullptr);
    // 9. fused cross-attention (half2) -> ofh fp16
    ca_attn_k<<<dim3(NB * 8, 4), 256>>>();
    // 10. h2 = o @ ca_wo^T + ca_bo + h1 -> h2h fp16
    gemm(ofh, (long)HW * INNER, INNER, wh_cao, 0, INNER, nullptr, h2h, nullptr,
         ca_bo, h1, 1.f, 1.f, HW, INNER, INNER, INNER, 0, nullptr, nullptr, nullptr);
    // 11. out = h2 @ w_out^T + b_out + x (mode 1 -> NCHW fp32, staged)
    gemm(h2h, (long)HW * INNER, INNER, wh_out, 0, INNER, out, nullptr, nullptr,
         b_out, x, 1.f, 1.f, HW, CIN, INNER, CIN, 1, nullptr, nullptr, nullptr);
}

// round 14
// speedup vs baseline: 1.1295x; 1.1295x over previous
#include <cuda_runtime.h>
#include <cuda_fp16.h>
#include <math.h>
#include <stdint.h>

#define NB    16
#define CIN   256
#define HW    1024
#define INNER 512
#define CTXN  77
#define CTXD  768
#define DH    64

// ===================== PTX helpers (sm_80-safe only) =========================
__device__ __forceinline__ uint32_t smem_to_u32(const void* p) {
    uint32_t a;
    asm("{ .reg .u64 t; cvta.to.shared.u64 t, %1; cvt.u32.u64 %0, t; }" : "=r"(a) : "l"(p));
    return a;
}
__device__ __forceinline__ void cp16(uint32_t dst, const void* src, bool valid) {
    int sz = valid ? 16 : 0;
    asm volatile("cp.async.cg.shared.global [%0], [%1], 16, %2;"
                 :: "r"(dst), "l"(src), "r"(sz) : "memory");
}
#define CP_COMMIT() asm volatile("cp.async.commit_group;" ::: "memory")
template <int N>
__device__ __forceinline__ void cp_wait() {
    asm volatile("cp.async.wait_group %0;" :: "n"(N) : "memory");
}
__device__ __forceinline__ void ldsm_x4(uint32_t* r, uint32_t addr) {
    asm volatile("ldmatrix.sync.aligned.m8n8.x4.shared.b16 {%0,%1,%2,%3}, [%4];"
        : "=r"(r[0]), "=r"(r[1]), "=r"(r[2]), "=r"(r[3]) : "r"(addr));
}
__device__ __forceinline__ void mma_f16(float* d, const uint32_t* a,
                                        uint32_t b0, uint32_t b1) {
    asm volatile(
        "mma.sync.aligned.m16n8k16.row.col.f32.f16.f16.f32 "
        "{%0,%1,%2,%3}, {%4,%5,%6,%7}, {%8,%9}, {%0,%1,%2,%3};"
        : "+f"(d[0]), "+f"(d[1]), "+f"(d[2]), "+f"(d[3])
        : "r"(a[0]), "r"(a[1]), "r"(a[2]), "r"(a[3]), "r"(b0), "r"(b1));
}

// ===================== scratch (device globals) ==============================
#define WH_TOTAL 3567616L
__device__ __align__(16) __half g_wh[WH_TOTAL];            // fp16 weights + ctx
__device__ __align__(16) float g_h0 [NB * HW * INNER];     // conv_in out (fp32)
__device__ __align__(16) float g_h1 [NB * HW * INNER];     // after SA (fp32)
__device__ __align__(16) float g_kvc[NB * CTXN * 1024];
__device__ __align__(16) float g_rsum[NB * HW];            // softmax row sums
__device__ float g_stats[NB * 32 * 2];
__device__ __align__(16) __half g_xnh [NB * HW * CIN];
__device__ __align__(16) __half g_hnh [NB * HW * INNER];
__device__ __align__(16) __half g_qkh [NB * HW * 1024];    // q|k merged
__device__ __align__(16) __half g_qh  [NB * HW * INNER];   // CA q
__device__ __align__(16) __half g_vth [NB * HW * INNER];   // v^T
__device__ __align__(16) __half g_oh  [NB * HW * INNER];   // SA attn out
__device__ __align__(16) __half g_h1h [NB * HW * INNER];
__device__ __align__(16) __half g_h2h [NB * HW * INNER];
__device__ __align__(16) __half g_ofh [NB * HW * INNER];   // CA attn out
__device__ __align__(16) __half g_attn[(long)NB * HW * HW];

// ===================== reductions ============================================
__device__ __forceinline__ float warpSum(float v) {
#pragma unroll
    for (int o = 16; o; o >>= 1) v += __shfl_xor_sync(0xffffffffu, v, o);
    return v;
}
__device__ float blockSum(float v) {
    __shared__ float sm[8];
    int t = threadIdx.x;
    v = warpSum(v);
    if ((t & 31) == 0) sm[t >> 5] = v;
    __syncthreads();
    if (t < 32) {
        float w = (t < 8) ? sm[t] : 0.f;
        w = warpSum(w);
        if (t == 0) sm[0] = w;
    }
    __syncthreads();
    float r = sm[0];
    __syncthreads();
    return r;
}

// ===================== conversions ===========================================
struct CvtSrc { const float* p[11]; };
__global__ void cvt_k(CvtSrc a) {
    long i = (long)blockIdx.x * 256 + threadIdx.x;
    if (i >= WH_TOTAL) return;
    const long ends[11] = {131072, 393216, 655360, 917504, 1179648, 1441792,
                           1835008, 2228224, 2490368, 2621440, 3567616};
    int s = 0; long off = 0;
#pragma unroll
    for (int k = 0; k < 11; k++) {
        if (i >= ends[k]) { s = k + 1; off = ends[k]; }
    }
    g_wh[i] = __float2half_rn(a.p[s][i - off]);
}

// ===================== GroupNorm 1 ===========================================
__global__ void gn1_stats_k(const float* __restrict__ x) {
    int bg = blockIdx.x;
    // zero softmax row-sum buffer (runs first every replay)
    if (threadIdx.x < 32) g_rsum[bg * 32 + threadIdx.x] = 0.f;
    const float* p = x + (long)bg * 8192;
    float s = 0.f, ss = 0.f;
    for (int i = threadIdx.x; i < 2048; i += 256) {
        float4 v = ((const float4*)p)[i];
        s += v.x + v.y + v.z + v.w;
        ss += v.x * v.x + v.y * v.y + v.z * v.z + v.w * v.w;
    }
    s = blockSum(s); ss = blockSum(ss);
    if (threadIdx.x == 0) {
        float mean = s * (1.f / 8192.f);
        float var  = ss * (1.f / 8192.f) - mean * mean;
        g_stats[bg * 2]     = mean;
        g_stats[bg * 2 + 1] = rsqrtf(var + 1e-5f);
    }
}
// tiled transpose + normalize: x [b][c][n] fp32 -> xnh [b][n][c] fp16
__global__ void gn1_apply_k(const float* __restrict__ x,
                            const float* __restrict__ gam,
                            const float* __restrict__ bet) {
    __shared__ float t[32][33];
    int b = blockIdx.z;
    int c0 = blockIdx.y * 32;
    int n0 = blockIdx.x * 32;
    int tx = threadIdx.x, ty = threadIdx.y;
#pragma unroll
    for (int i = 0; i < 4; i++) {
        int c = c0 + ty + i * 8;
        float v = x[((long)(b * 256 + c) << 10) + n0 + tx];
        int sg = (b << 5) | (c >> 3);
        t[ty + i * 8][tx] = (v - g_stats[sg * 2]) * g_stats[sg * 2 + 1] * gam[c] + bet[c];
    }
    __syncthreads();
#pragma unroll
    for (int i = 0; i < 4; i++) {
        int n = n0 + ty + i * 8;
        g_xnh[((long)(b * 1024 + n) << 8) + c0 + tx] = __float2half_rn(t[tx][ty + i * 8]);
    }
}

// ===================== GroupNorm 2 (h0 fp32 -> hnh fp16) =====================
// One block per (b, group): 512 blocks — chip stays full (R12 config).
__global__ void gn2_k(const float* __restrict__ gg, const float* __restrict__ gb) {
    int b = blockIdx.x >> 5, g = blockIdx.x & 31;
    const float4* p = (const float4*)(g_h0 + (long)b * HW * INNER + g * 16);
    float s = 0.f, ss = 0.f;
    for (int i = threadIdx.x; i < HW * 4; i += 256) {
        int n = i >> 2, j = i & 3;
        float4 v = p[n * 128 + j];
        s += v.x + v.y + v.z + v.w;
        ss += v.x * v.x + v.y * v.y + v.z * v.z + v.w * v.w;
    }
    s = blockSum(s); ss = blockSum(ss);
    float mean = s * (1.f / 16384.f);
    float rstd = rsqrtf(ss * (1.f / 16384.f) - mean * mean + 1e-5f);
    __half* q = g_hnh + (long)b * HW * INNER + g * 16;
    for (int i = threadIdx.x; i < HW * 4; i += 256) {
        int n = i >> 2, j = i & 3;
        int c = g * 16 + j * 4;
        float4 v = p[n * 128 + j];
        __half2 h0 = __floats2half2_rn(
            (v.x - mean) * rstd * gg[c] + gb[c],
            (v.y - mean) * rstd * gg[c + 1] + gb[c + 1]);
        __half2 h1 = __floats2half2_rn(
            (v.z - mean) * rstd * gg[c + 2] + gb[c + 2],
            (v.w - mean) * rstd * gg[c + 3] + gb[c + 3]);
        *(uint2*)(q + n * INNER + j * 4) = make_uint2(
            *(uint32_t*)&h0, *(uint32_t*)&h1);
    }
}

// ===================== fused cross-attention (half2 math) ====================
__global__ void __launch_bounds__(256) ca_attn_k() {
    __shared__ __half2 Ks[CTXN][DH / 2];
    __shared__ __half2 Vs[CTXN][DH / 2];
    int b = blockIdx.x >> 3, h = blockIdx.x & 7;
    const float2* kp = (const float2*)(g_kvc + (long)b * CTXN * 1024 + h * DH);
    const float2* vp = (const float2*)(g_kvc + (long)b * CTXN * 1024 + 512 + h * DH);
    for (int i = threadIdx.x; i < CTXN * 32; i += 256) {
        int j = i >> 5, d = i & 31;
        float2 kf = kp[j * 512 + d];
        float2 vf = vp[j * 512 + d];
        Ks[j][d] = __floats2half2_rn(kf.x, kf.y);
        Vs[j][d] = __floats2half2_rn(vf.x, vf.y);
    }
    __syncthreads();
    int i = blockIdx.y * 256 + threadIdx.x;
    const __half2* qp = (const __half2*)(g_qh + ((long)(b * HW + i)) * INNER + h * DH);
    __half2 qv[32];
    uint4* qv4 = (uint4*)qv;
#pragma unroll
    for (int d = 0; d < 8; d++) qv4[d] = ((const uint4*)qp)[d];

    float l = 0.f;
    __half2 acc[32];
    const __half2 z2 = __float2half2_rn(0.f);
#pragma unroll
    for (int d = 0; d < 32; d++) acc[d] = z2;
    for (int j = 0; j < CTXN; j++) {
        __half2 d2 = __hmul2(qv[0], Ks[j][0]);
#pragma unroll
        for (int d = 1; d < 32; d++) d2 = __hfma2(qv[d], Ks[j][d], d2);
        float s = (__low2float(d2) + __high2float(d2)) * 0.125f;
        float e = __expf(s);
        l += e;
        __half2 e2 = __float2half2_rn(e);
#pragma unroll
        for (int d = 0; d < 32; d++) acc[d] = __hfma2(e2, Vs[j][d], acc[d]);
    }
    float inv = 1.f / l;
    __half* op = g_ofh + ((long)(b * HW + i)) * INNER + h * DH;
#pragma unroll
    for (int d = 0; d < 32; d += 4) {
        __half2 pk[4];
#pragma unroll
        for (int e = 0; e < 4; e++) {
            float2 a = __half22float2(acc[d + e]);
            pk[e] = __floats2half2_rn(a.x * inv, a.y * inv);
        }
        *(uint4*)(op + d * 2) = *(uint4*)pk;
    }
}

// ===================== fp16 mma.sync GEMM (template modes) ===================
// MODE 0: C row-major (stride ldc); optional rsum/rdiv (fused softmax), bias, R.
// MODE 1: C transposed [N, M] per batch (staged, coalesced), Cf/Cb.
// MODE 2: merged qkv — bn<1024: Cb row-major (ldc=1024); bn>=1024: v^T into
//         Cb2 (per-batch 512x1024), staged transpose.
// CTA 128x128, 8 warps (2x4, 64x32), BK=64, 3 stages x 32KB, 2 CTAs/SM.
#define STAGE_B 32768
#define GSMEM   98304

__device__ __forceinline__ void frag_load(
    uint32_t aT, uint32_t bT, int wm, int wn, int lane, int kk,
    uint32_t af[4][4], uint32_t bfr[2][4]) {
    const int r0 = lane & 15;
    const int uu = kk * 2 + (lane >> 4);
#pragma unroll
    for (int mi = 0; mi < 4; mi++) {
        int r = wm + mi * 16 + r0;
        ldsm_x4(af[mi], aT + r * 128 + ((uu ^ (r & 7)) << 4));
    }
#pragma unroll
    for (int p = 0; p < 2; p++) {
        int r = wn + p * 16 + r0;
        ldsm_x4(bfr[p], bT + r * 128 + ((uu ^ (r & 7)) << 4));
    }
}

template <int MODE>
__global__ void __launch_bounds__(256, 2) gemm_mma(
    const __half* __restrict__ A_, long sA, int lda,
    const __half* __restrict__ B_, long sB, int ldb,
    float* __restrict__ Cf, __half* __restrict__ Cb, __half* __restrict__ Cb2,
    const float* __restrict__ bias, const float* __restrict__ R,
    float rcoef, float alpha, int M, int N, int K, int ldc,
    float* __restrict__ rsum, const float* __restrict__ rdiv) {
    extern __shared__ __align__(128) char sm[];
    const uint32_t sb = smem_to_u32(sm);
    const int tid  = threadIdx.x;
    const int lane = tid & 31;
    const int wid  = tid >> 5;
    const int bz = blockIdx.z;
    const int bm = blockIdx.y * 128;
    const int bn = blockIdx.x * 128;
    const int wm = (wid >> 2) * 64;
    const int wn = (wid & 3) * 32;
    const __half* Ab = A_ + (long)bz * sA;
    const __half* Bb = B_ + (long)bz * sB;

    float acc[4][4][4];
#pragma unroll
    for (int i = 0; i < 4; i++)
#pragma unroll
        for (int j = 0; j < 4; j++)
#pragma unroll
            for (int e = 0; e < 4; e++) acc[i][j][e] = 0.f;

    const int lrow = tid >> 1;
    const int lu0  = (tid & 1) * 4;
    const bool aValid = (bm + lrow) < M;
    const long aOff = aValid ? (long)(bm + lrow) * lda : 0;
    const long bOff = (long)(bn + lrow) * ldb;
    const int nIter = K >> 6;

#define LOADC(i, s) do {                                                        \
    uint32_t dA = sb + (s) * STAGE_B + lrow * 128;                              \
    uint32_t dB = dA + 16384;                                                   \
    const __half* gA = Ab + aOff + ((long)(i) << 6);                            \
    const __half* gB = Bb + bOff + ((long)(i) << 6);                            \
    _Pragma("unroll")                                                           \
    for (int j = 0; j < 4; j++) {                                               \
        int u = lu0 + j;                                                        \
        uint32_t so = (uint32_t)((u ^ (lrow & 7)) << 4);                        \
        cp16(dA + so, gA + u * 8, aValid);                                      \
        cp16(dB + so, gB + u * 8, true);                                        \
    }                                                                           \
} while (0)

    LOADC(0, 0); CP_COMMIT();
    if (1 < nIter) { LOADC(1, 1); }
    CP_COMMIT();

    uint32_t af[4][4], bfr[2][4];

    for (int it = 0; it < nIter; it++) {
        const int s = it % 3;
        if (it + 1 < nIter) cp_wait<1>(); else cp_wait<0>();
        __syncthreads();
        if (it + 2 < nIter) { LOADC(it + 2, (it + 2) % 3); CP_COMMIT(); }

        const uint32_t aT = sb + s * STAGE_B;
        const uint32_t bT = aT + 16384;
#pragma unroll
        for (int kk = 0; kk < 4; kk++) {
            frag_load(aT, bT, wm, wn, lane, kk, af, bfr);
#pragma unroll
            for (int mi = 0; mi < 4; mi++)
#pragma unroll
                for (int p = 0; p < 2; p++) {
                    mma_f16(acc[mi][2 * p],     af[mi], bfr[p][0], bfr[p][2]);
                    mma_f16(acc[mi][2 * p + 1], af[mi], bfr[p][1], bfr[p][3]);
                }
        }
        __syncthreads();
    }

    // ------------------------------ epilogue ------------------------------
    const int tr = lane >> 2;
    const int tc = (lane & 3) * 2;
    const bool staged = (MODE == 1) || (MODE == 2 && bn >= 1024);
    if (staged) {
        float* st = (float*)sm;
#pragma unroll
        for (int mi = 0; mi < 4; mi++)
#pragma unroll
            for (int r2 = 0; r2 < 2; r2++) {
                const int ml = wm + mi * 16 + tr + r2 * 8;
#pragma unroll
                for (int nj = 0; nj < 4; nj++) {
                    const int nl = wn + nj * 8 + tc;
                    st[nl * 132 + ml]       = acc[mi][nj][r2 * 2 + 0] * alpha;
                    st[(nl + 1) * 132 + ml] = acc[mi][nj][r2 * 2 + 1] * alpha;
                }
            }
        __syncthreads();
        if (MODE == 1) {
            const long bzMN = (long)bz * M * N;
#pragma unroll
            for (int r = 0; r < 16; r++) {
                const int nl = wid * 16 + r;
                const int n = bn + nl;
                float bv = bias ? bias[n] : 0.f;
                float4 v = *(float4*)&st[nl * 132 + lane * 4];
                v.x += bv; v.y += bv; v.z += bv; v.w += bv;
                const long i0 = bzMN + (long)n * M + bm + lane * 4;
                if (R) {
                    float4 rv = *(const float4*)(R + i0);
                    v.x += rcoef * rv.x; v.y += rcoef * rv.y;
                    v.z += rcoef * rv.z; v.w += rcoef * rv.w;
                }
                if (Cf) *(float4*)(Cf + i0) = v;
                if (Cb) {
                    __half2 h0v = __floats2half2_rn(v.x, v.y);
                    __half2 h1v = __floats2half2_rn(v.z, v.w);
                    *(uint2*)(Cb + i0) = make_uint2(*(uint32_t*)&h0v, *(uint32_t*)&h1v);
                }
            }
        } else {
            // MODE 2, v part: write transposed into Cb2 (v^T per batch 512x1024)
#pragma unroll
            for (int r = 0; r < 16; r++) {
                const int nl = wid * 16 + r;
                const int vrow = bn - 1024 + nl;
                float4 v = *(float4*)&st[nl * 132 + lane * 4];
                __half2 h0v = __floats2half2_rn(v.x, v.y);
                __half2 h1v = __floats2half2_rn(v.z, v.w);
                const long i0 = (long)bz * 524288 + (long)vrow * 1024 + bm + lane * 4;
                *(uint2*)(Cb2 + i0) = make_uint2(*(uint32_t*)&h0v, *(uint32_t*)&h1v);
            }
        }
    } else {
        const long bzC = (long)bz * M * ldc;
#pragma unroll
        for (int mi = 0; mi < 4; mi++) {
#pragma unroll
            for (int r2 = 0; r2 < 2; r2++) {
                const int m = bm + wm + mi * 16 + tr + r2 * 8;
                if (m >= M) continue;
                float rAcc = 0.f;
                float inv = 1.f;
                if (rdiv) inv = 1.f / rdiv[(long)bz * M + m];
#pragma unroll
                for (int nj = 0; nj < 4; nj++) {
                    const int n = bn + wn + nj * 8 + tc;
                    float v0 = acc[mi][nj][r2 * 2 + 0] * alpha;
                    float v1 = acc[mi][nj][r2 * 2 + 1] * alpha;
                    if (bias) { v0 += bias[n]; v1 += bias[n + 1]; }
                    if (rsum) {
                        v0 = __expf(v0); v1 = __expf(v1);
                        rAcc += v0 + v1;
                    }
                    v0 *= inv; v1 *= inv;
                    const long i0 = bzC + (long)m * ldc + n;
                    if (R) {
                        float2 rv = *(const float2*)(R + i0);
                        v0 += rcoef * rv.x; v1 += rcoef * rv.y;
                    }
                    if (Cf) *(float2*)(Cf + i0) = make_float2(v0, v1);
                    if (Cb) {
                        __half2 hv = __floats2half2_rn(v0, v1);
                        *(uint32_t*)(Cb + i0) = *(uint32_t*)&hv;
                    }
                }
                if (rsum) {
                    rAcc += __shfl_xor_sync(0xffffffffu, rAcc, 1);
                    rAcc += __shfl_xor_sync(0xffffffffu, rAcc, 2);
                    if ((lane & 3) == 0)
                        atomicAdd(&rsum[(long)bz * M + m], rAcc);
                }
            }
        }
    }
#undef LOADC
}

template <int MODE>
static void gemm(const __half* A, long sA, int lda,
                 const __half* B, long sB, int ldb,
                 float* Cf, __half* Cb, __half* Cb2,
                 const float* bias, const float* R,
                 float rcoef, float alpha, int M, int N, int K, int ldc,
                 float* rsum, const float* rdiv) {
    cudaFuncSetAttribute(gemm_mma<MODE>, cudaFuncAttributeMaxDynamicSharedMemorySize, GSMEM);
    dim3 grid(N / 128, (M + 127) / 128, NB);
    gemm_mma<MODE><<<grid, 256, GSMEM>>>(A, sA, lda, B, sB, ldb, Cf, Cb, Cb2,
                                         bias, R, rcoef, alpha, M, N, K, ldc,
                                         rsum, rdiv);
}

// ===================== driver ================================================
extern "C" void kernel_launch(void* const* d_in, const int* in_sizes, int n_in,
                              void* d_out, int out_size) {
    const float* x      = (const float*)d_in[0];
    const float* ctx    = (const float*)d_in[1];
    const float* gn1_g  = (const float*)d_in[2];
    const float* gn1_b  = (const float*)d_in[3];
    const float* w_in   = (const float*)d_in[4];
    const float* b_in   = (const float*)d_in[5];
    const float* sa_wk  = (const float*)d_in[6];
    const float* sa_wq  = (const float*)d_in[7];
    const float* sa_wv  = (const float*)d_in[8];
    const float* sa_wp  = (const float*)d_in[9];
    const float* sa_gng = (const float*)d_in[10];
    const float* sa_gnb = (const float*)d_in[11];
    const float* ca_wq  = (const float*)d_in[12];
    const float* ca_wk  = (const float*)d_in[13];
    const float* ca_wv  = (const float*)d_in[14];
    const float* ca_wo  = (const float*)d_in[15];
    const float* ca_bo  = (const float*)d_in[16];
    const float* w_out  = (const float*)d_in[17];
    const float* b_out  = (const float*)d_in[18];
    float* out = (float*)d_out;

    float *h0, *h1, *kvc, *rs;
    __half *wh, *xnh, *hnh, *qkh, *qh, *vth, *oh, *h1h, *h2h, *ofh, *attnh;
    cudaGetSymbolAddress((void**)&h0,  g_h0);
    cudaGetSymbolAddress((void**)&h1,  g_h1);
    cudaGetSymbolAddress((void**)&kvc, g_kvc);
    cudaGetSymbolAddress((void**)&rs,  g_rsum);
    cudaGetSymbolAddress((void**)&wh,  g_wh);
    cudaGetSymbolAddress((void**)&xnh, g_xnh);
    cudaGetSymbolAddress((void**)&hnh, g_hnh);
    cudaGetSymbolAddress((void**)&qkh, g_qkh);
    cudaGetSymbolAddress((void**)&qh,  g_qh);
    cudaGetSymbolAddress((void**)&vth, g_vth);
    cudaGetSymbolAddress((void**)&oh,  g_oh);
    cudaGetSymbolAddress((void**)&h1h, g_h1h);
    cudaGetSymbolAddress((void**)&h2h, g_h2h);
    cudaGetSymbolAddress((void**)&ofh, g_ofh);
    cudaGetSymbolAddress((void**)&attnh, g_attn);

    __half* wh_in   = wh;
    __half* wh_qkv  = wh + 131072;     // sa_wq | sa_wk | sa_wv contiguous [1536,512]
    __half* wh_sap  = wh + 917504;
    __half* wh_caq  = wh + 1179648;
    __half* wh_cakv = wh + 1441792;    // ca_wk | ca_wv [1024,768]
    __half* wh_cao  = wh + 2228224;
    __half* wh_out  = wh + 2490368;
    __half* ctx_h   = wh + 2621440;

    const float inv_sqrt_c = 0.044194173824159216f;   // 512^-0.5

    // 0. convert weights + ctx to fp16
    CvtSrc cs;
    cs.p[0] = w_in;  cs.p[1] = sa_wq; cs.p[2] = sa_wk; cs.p[3] = sa_wv;
    cs.p[4] = sa_wp; cs.p[5] = ca_wq; cs.p[6] = ca_wk; cs.p[7] = ca_wv;
    cs.p[8] = ca_wo; cs.p[9] = w_out; cs.p[10] = ctx;
    cvt_k<<<(int)((WH_TOTAL + 255) / 256), 256>>>(cs);

    // 1. GN1(x) -> xnh fp16 [b,n,c] (also zeroes rsum)
    gn1_stats_k<<<NB * 32, 256>>>(x);
    gn1_apply_k<<<dim3(32, 8, NB), dim3(32, 8)>>>(x, gn1_g, gn1_b);
    // 2. conv_in: h0 = xn @ w_in^T + b_in (fp32)
    gemm<0>(xnh, (long)HW * CIN, CIN, wh_in, 0, CIN, h0, nullptr, nullptr,
            b_in, nullptr, 0.f, 1.f, HW, INNER, CIN, INNER, nullptr, nullptr);
    // 3. GN2(h0) -> hnh fp16 (two-pass, 512 blocks — R12 proven)
    gn2_k<<<NB * 32, 256>>>(sa_gng, sa_gnb);
    // 4. merged q|k|v: N=1536; q|k -> qkh (ldc=1024), v -> vth transposed
    gemm<2>(hnh, (long)HW * INNER, INNER, wh_qkv, 0, INNER, nullptr, qkh, vth,
            nullptr, nullptr, 0.f, 1.f, HW, 1536, INNER, 1024, nullptr, nullptr);
    // 5. attn_unnorm = exp(q @ k^T * c^-0.5); rowsums accumulated
    gemm<0>(qkh, (long)HW * 1024, 1024, qkh + 512, (long)HW * 1024, 1024,
            nullptr, attnh, nullptr, nullptr, nullptr, 0.f, inv_sqrt_c,
            HW, HW, INNER, HW, rs, nullptr);
    // 6. o = (exp_attn @ v) / rowsum -> oh fp16
    gemm<0>(attnh, (long)HW * HW, HW, vth, (long)INNER * HW, HW,
            nullptr, oh, nullptr, nullptr, nullptr, 0.f, 1.f,
            HW, INNER, HW, INNER, nullptr, rs);
    // 7. h1 = o @ wp^T + 2*h0 (fp32 + fp16 copies)
    gemm<0>(oh, (long)HW * INNER, INNER, wh_sap, 0, INNER, h1, h1h, nullptr,
            nullptr, h0, 2.f, 1.f, HW, INNER, INNER, INNER, nullptr, nullptr);
    // 8. CA projections: q fp16, fused k|v fp32
    gemm<0>(h1h, (long)HW * INNER, INNER, wh_caq, 0, INNER, nullptr, qh, nullptr,
            nullptr, nullptr, 0.f, 1.f, HW, INNER, INNER, INNER, nullptr, nullptr);
    gemm<0>(ctx_h, (long)CTXN * CTXD, CTXD, wh_cakv, 0, CTXD, kvc, nullptr, nullptr,
            nullptr, nullptr, 0.f, 1.f, CTXN, 1024, CTXD, 1024, nullptr, nullptr);
    // 9. fused cross-attention (half2) -> ofh fp16
    ca_attn_k<<<dim3(NB * 8, 4), 256>>>();
    // 10. h2 = o @ ca_wo^T + ca_bo + h1 -> h2h fp16
    gemm<0>(ofh, (long)HW * INNER, INNER, wh_cao, 0, INNER, nullptr, h2h, nullptr,
            ca_bo, h1, 1.f, 1.f, HW, INNER, INNER, INNER, nullptr, nullptr);
    // 11. out = h2 @ w_out^T + b_out + x (MODE 1 -> NCHW fp32, staged)
    gemm<1>(h2h, (long)HW * INNER, INNER, wh_out, 0, INNER, out, nullptr, nullptr,
            b_out, x, 1.f, 1.f, HW, CIN, INNER, CIN, nullptr, nullptr);
}

// round 15
// speedup vs baseline: 1.1370x; 1.0066x over previous
#include <cuda_runtime.h>
#include <cuda_fp16.h>
#include <math.h>
#include <stdint.h>

#define NB    16
#define CIN   256
#define HW    1024
#define INNER 512
#define CTXN  77
#define CTXD  768
#define DH    64

// ===================== PTX helpers (sm_80-safe only) =========================
__device__ __forceinline__ uint32_t smem_to_u32(const void* p) {
    uint32_t a;
    asm("{ .reg .u64 t; cvta.to.shared.u64 t, %1; cvt.u32.u64 %0, t; }" : "=r"(a) : "l"(p));
    return a;
}
__device__ __forceinline__ void cp16(uint32_t dst, const void* src, bool valid) {
    int sz = valid ? 16 : 0;
    asm volatile("cp.async.cg.shared.global [%0], [%1], 16, %2;"
                 :: "r"(dst), "l"(src), "r"(sz) : "memory");
}
#define CP_COMMIT() asm volatile("cp.async.commit_group;" ::: "memory")
template <int N>
__device__ __forceinline__ void cp_wait() {
    asm volatile("cp.async.wait_group %0;" :: "n"(N) : "memory");
}
__device__ __forceinline__ void ldsm_x4(uint32_t* r, uint32_t addr) {
    asm volatile("ldmatrix.sync.aligned.m8n8.x4.shared.b16 {%0,%1,%2,%3}, [%4];"
        : "=r"(r[0]), "=r"(r[1]), "=r"(r[2]), "=r"(r[3]) : "r"(addr));
}
__device__ __forceinline__ void mma_f16(float* d, const uint32_t* a,
                                        uint32_t b0, uint32_t b1) {
    asm volatile(
        "mma.sync.aligned.m16n8k16.row.col.f32.f16.f16.f32 "
        "{%0,%1,%2,%3}, {%4,%5,%6,%7}, {%8,%9}, {%0,%1,%2,%3};"
        : "+f"(d[0]), "+f"(d[1]), "+f"(d[2]), "+f"(d[3])
        : "r"(a[0]), "r"(a[1]), "r"(a[2]), "r"(a[3]), "r"(b0), "r"(b1));
}

// ===================== scratch (device globals) ==============================
#define WH_TOTAL 3567616L
__device__ __align__(16) __half g_wh[WH_TOTAL];            // fp16 weights + ctx
__device__ __align__(16) float g_h0 [NB * HW * INNER];     // conv_in out (fp32)
__device__ __align__(16) float g_h1 [NB * HW * INNER];     // after SA (fp32)
__device__ __align__(16) float g_kvc[NB * CTXN * 1024];
__device__ __align__(16) float g_rsum[NB * HW];            // softmax row sums
__device__ __align__(16) float g_gst[NB * 32 * 2];         // GN2 group s/ss
__device__ float g_stats[NB * 32 * 2];
__device__ __align__(16) __half g_xnh [NB * HW * CIN];
__device__ __align__(16) __half g_hnh [NB * HW * INNER];
__device__ __align__(16) __half g_qkh [NB * HW * 1024];    // q|k merged
__device__ __align__(16) __half g_qh  [NB * HW * INNER];   // CA q
__device__ __align__(16) __half g_vth [NB * HW * INNER];   // v^T
__device__ __align__(16) __half g_oh  [NB * HW * INNER];   // SA attn out
__device__ __align__(16) __half g_h1h [NB * HW * INNER];
__device__ __align__(16) __half g_h2h [NB * HW * INNER];
__device__ __align__(16) __half g_ofh [NB * HW * INNER];   // CA attn out
__device__ __align__(16) __half g_attn[(long)NB * HW * HW];

// ===================== reductions ============================================
__device__ __forceinline__ float warpSum(float v) {
#pragma unroll
    for (int o = 16; o; o >>= 1) v += __shfl_xor_sync(0xffffffffu, v, o);
    return v;
}
__device__ float blockSum(float v) {
    __shared__ float sm[8];
    int t = threadIdx.x;
    v = warpSum(v);
    if ((t & 31) == 0) sm[t >> 5] = v;
    __syncthreads();
    if (t < 32) {
        float w = (t < 8) ? sm[t] : 0.f;
        w = warpSum(w);
        if (t == 0) sm[0] = w;
    }
    __syncthreads();
    float r = sm[0];
    __syncthreads();
    return r;
}

// ===================== conversions ===========================================
struct CvtSrc { const float* p[11]; };
__global__ void cvt_k(CvtSrc a) {
    long i = (long)blockIdx.x * 256 + threadIdx.x;
    if (i >= WH_TOTAL) return;
    const long ends[11] = {131072, 393216, 655360, 917504, 1179648, 1441792,
                           1835008, 2228224, 2490368, 2621440, 3567616};
    int s = 0; long off = 0;
#pragma unroll
    for (int k = 0; k < 11; k++) {
        if (i >= ends[k]) { s = k + 1; off = ends[k]; }
    }
    g_wh[i] = __float2half_rn(a.p[s][i - off]);
}

// ===================== GroupNorm 1 ===========================================
__global__ void gn1_stats_k(const float* __restrict__ x) {
    int bg = blockIdx.x;
    // zero per-replay accumulators (this kernel runs first)
    if (threadIdx.x < 32) g_rsum[bg * 32 + threadIdx.x] = 0.f;
    if (threadIdx.x < 2)  g_gst[bg * 2 + threadIdx.x] = 0.f;
    const float* p = x + (long)bg * 8192;
    float s = 0.f, ss = 0.f;
    for (int i = threadIdx.x; i < 2048; i += 256) {
        float4 v = ((const float4*)p)[i];
        s += v.x + v.y + v.z + v.w;
        ss += v.x * v.x + v.y * v.y + v.z * v.z + v.w * v.w;
    }
    s = blockSum(s); ss = blockSum(ss);
    if (threadIdx.x == 0) {
        float mean = s * (1.f / 8192.f);
        float var  = ss * (1.f / 8192.f) - mean * mean;
        g_stats[bg * 2]     = mean;
        g_stats[bg * 2 + 1] = rsqrtf(var + 1e-5f);
    }
}
// tiled transpose + normalize: x [b][c][n] fp32 -> xnh [b][n][c] fp16
__global__ void gn1_apply_k(const float* __restrict__ x,
                            const float* __restrict__ gam,
                            const float* __restrict__ bet) {
    __shared__ float t[32][33];
    int b = blockIdx.z;
    int c0 = blockIdx.y * 32;
    int n0 = blockIdx.x * 32;
    int tx = threadIdx.x, ty = threadIdx.y;
#pragma unroll
    for (int i = 0; i < 4; i++) {
        int c = c0 + ty + i * 8;
        float v = x[((long)(b * 256 + c) << 10) + n0 + tx];
        int sg = (b << 5) | (c >> 3);
        t[ty + i * 8][tx] = (v - g_stats[sg * 2]) * g_stats[sg * 2 + 1] * gam[c] + bet[c];
    }
    __syncthreads();
#pragma unroll
    for (int i = 0; i < 4; i++) {
        int n = n0 + ty + i * 8;
        g_xnh[((long)(b * 1024 + n) << 8) + c0 + tx] = __float2half_rn(t[tx][ty + i * 8]);
    }
}

// ===================== GroupNorm 2 apply (stats fused into conv_in) ==========
// Single pass over h0; stats come from conv_in's MODE-3 epilogue atomics.
__global__ void gn2_apply_k(const float* __restrict__ gg,
                            const float* __restrict__ gb) {
    int b = blockIdx.x >> 5, g = blockIdx.x & 31;
    float s  = g_gst[(b * 32 + g) * 2];
    float ss = g_gst[(b * 32 + g) * 2 + 1];
    float mean = s * (1.f / 16384.f);
    float rstd = rsqrtf(ss * (1.f / 16384.f) - mean * mean + 1e-5f);
    const float4* p = (const float4*)(g_h0 + (long)b * HW * INNER + g * 16);
    __half* q = g_hnh + (long)b * HW * INNER + g * 16;
    for (int i = threadIdx.x; i < HW * 4; i += 256) {
        int n = i >> 2, j = i & 3;
        int c = g * 16 + j * 4;
        float4 v = p[n * 128 + j];
        __half2 h0 = __floats2half2_rn(
            (v.x - mean) * rstd * gg[c] + gb[c],
            (v.y - mean) * rstd * gg[c + 1] + gb[c + 1]);
        __half2 h1 = __floats2half2_rn(
            (v.z - mean) * rstd * gg[c + 2] + gb[c + 2],
            (v.w - mean) * rstd * gg[c + 3] + gb[c + 3]);
        *(uint2*)(q + n * INNER + j * 4) = make_uint2(
            *(uint32_t*)&h0, *(uint32_t*)&h1);
    }
}

// ===================== fused cross-attention (half2 math) ====================
__global__ void __launch_bounds__(256) ca_attn_k() {
    __shared__ __half2 Ks[CTXN][DH / 2];
    __shared__ __half2 Vs[CTXN][DH / 2];
    int b = blockIdx.x >> 3, h = blockIdx.x & 7;
    const float2* kp = (const float2*)(g_kvc + (long)b * CTXN * 1024 + h * DH);
    const float2* vp = (const float2*)(g_kvc + (long)b * CTXN * 1024 + 512 + h * DH);
    for (int i = threadIdx.x; i < CTXN * 32; i += 256) {
        int j = i >> 5, d = i & 31;
        float2 kf = kp[j * 512 + d];
        float2 vf = vp[j * 512 + d];
        Ks[j][d] = __floats2half2_rn(kf.x, kf.y);
        Vs[j][d] = __floats2half2_rn(vf.x, vf.y);
    }
    __syncthreads();
    int i = blockIdx.y * 256 + threadIdx.x;
    const __half2* qp = (const __half2*)(g_qh + ((long)(b * HW + i)) * INNER + h * DH);
    __half2 qv[32];
    uint4* qv4 = (uint4*)qv;
#pragma unroll
    for (int d = 0; d < 8; d++) qv4[d] = ((const uint4*)qp)[d];

    float l = 0.f;
    __half2 acc[32];
    const __half2 z2 = __float2half2_rn(0.f);
#pragma unroll
    for (int d = 0; d < 32; d++) acc[d] = z2;
    for (int j = 0; j < CTXN; j++) {
        __half2 d2 = __hmul2(qv[0], Ks[j][0]);
#pragma unroll
        for (int d = 1; d < 32; d++) d2 = __hfma2(qv[d], Ks[j][d], d2);
        float s = (__low2float(d2) + __high2float(d2)) * 0.125f;
        float e = __expf(s);
        l += e;
        __half2 e2 = __float2half2_rn(e);
#pragma unroll
        for (int d = 0; d < 32; d++) acc[d] = __hfma2(e2, Vs[j][d], acc[d]);
    }
    float inv = 1.f / l;
    __half* op = g_ofh + ((long)(b * HW + i)) * INNER + h * DH;
#pragma unroll
    for (int d = 0; d < 32; d += 4) {
        __half2 pk[4];
#pragma unroll
        for (int e = 0; e < 4; e++) {
            float2 a = __half22float2(acc[d + e]);
            pk[e] = __floats2half2_rn(a.x * inv, a.y * inv);
        }
        *(uint4*)(op + d * 2) = *(uint4*)pk;
    }
}

// ===================== fp16 mma.sync GEMM (template modes) ===================
// MODE 0: C row-major (stride ldc); optional rsum/rdiv (fused softmax), bias, R.
// MODE 1: C transposed [N, M] per batch (staged, coalesced), Cf/Cb.
// MODE 2: merged qkv — bn<1024: Cb row-major (ldc=1024); bn>=1024: v^T into
//         Cb2 (per-batch 512x1024), staged transpose.
// MODE 3: MODE 0 + GN2 group stats: per-warp reduced s/ss atomics into gstats
//         (groups are warp-uniform: 16 atomics per address — contention-free).
// CTA 128x128, 8 warps (2x4, 64x32), BK=64, 3 stages x 32KB, 2 CTAs/SM.
#define STAGE_B 32768
#define GSMEM   98304

__device__ __forceinline__ void frag_load(
    uint32_t aT, uint32_t bT, int wm, int wn, int lane, int kk,
    uint32_t af[4][4], uint32_t bfr[2][4]) {
    const int r0 = lane & 15;
    const int uu = kk * 2 + (lane >> 4);
#pragma unroll
    for (int mi = 0; mi < 4; mi++) {
        int r = wm + mi * 16 + r0;
        ldsm_x4(af[mi], aT + r * 128 + ((uu ^ (r & 7)) << 4));
    }
#pragma unroll
    for (int p = 0; p < 2; p++) {
        int r = wn + p * 16 + r0;
        ldsm_x4(bfr[p], bT + r * 128 + ((uu ^ (r & 7)) << 4));
    }
}

template <int MODE>
__global__ void __launch_bounds__(256, 2) gemm_mma(
    const __half* __restrict__ A_, long sA, int lda,
    const __half* __restrict__ B_, long sB, int ldb,
    float* __restrict__ Cf, __half* __restrict__ Cb, __half* __restrict__ Cb2,
    const float* __restrict__ bias, const float* __restrict__ R,
    float rcoef, float alpha, int M, int N, int K, int ldc,
    float* __restrict__ rsum, const float* __restrict__ rdiv,
    float* __restrict__ gstats) {
    extern __shared__ __align__(128) char sm[];
    const uint32_t sb = smem_to_u32(sm);
    const int tid  = threadIdx.x;
    const int lane = tid & 31;
    const int wid  = tid >> 5;
    const int bz = blockIdx.z;
    const int bm = blockIdx.y * 128;
    const int bn = blockIdx.x * 128;
    const int wm = (wid >> 2) * 64;
    const int wn = (wid & 3) * 32;
    const __half* Ab = A_ + (long)bz * sA;
    const __half* Bb = B_ + (long)bz * sB;

    float acc[4][4][4];
#pragma unroll
    for (int i = 0; i < 4; i++)
#pragma unroll
        for (int j = 0; j < 4; j++)
#pragma unroll
            for (int e = 0; e < 4; e++) acc[i][j][e] = 0.f;

    const int lrow = tid >> 1;
    const int lu0  = (tid & 1) * 4;
    const bool aValid = (bm + lrow) < M;
    const long aOff = aValid ? (long)(bm + lrow) * lda : 0;
    const long bOff = (long)(bn + lrow) * ldb;
    const int nIter = K >> 6;

#define LOADC(i, s) do {                                                        \
    uint32_t dA = sb + (s) * STAGE_B + lrow * 128;                              \
    uint32_t dB = dA + 16384;                                                   \
    const __half* gA = Ab + aOff + ((long)(i) << 6);                            \
    const __half* gB = Bb + bOff + ((long)(i) << 6);                            \
    _Pragma("unroll")                                                           \
    for (int j = 0; j < 4; j++) {                                               \
        int u = lu0 + j;                                                        \
        uint32_t so = (uint32_t)((u ^ (lrow & 7)) << 4);                        \
        cp16(dA + so, gA + u * 8, aValid);                                      \
        cp16(dB + so, gB + u * 8, true);                                        \
    }                                                                           \
} while (0)

    LOADC(0, 0); CP_COMMIT();
    if (1 < nIter) { LOADC(1, 1); }
    CP_COMMIT();

    uint32_t af[4][4], bfr[2][4];

    for (int it = 0; it < nIter; it++) {
        const int s = it % 3;
        if (it + 1 < nIter) cp_wait<1>(); else cp_wait<0>();
        __syncthreads();
        if (it + 2 < nIter) { LOADC(it + 2, (it + 2) % 3); CP_COMMIT(); }

        const uint32_t aT = sb + s * STAGE_B;
        const uint32_t bT = aT + 16384;
#pragma unroll
        for (int kk = 0; kk < 4; kk++) {
            frag_load(aT, bT, wm, wn, lane, kk, af, bfr);
#pragma unroll
            for (int mi = 0; mi < 4; mi++)
#pragma unroll
                for (int p = 0; p < 2; p++) {
                    mma_f16(acc[mi][2 * p],     af[mi], bfr[p][0], bfr[p][2]);
                    mma_f16(acc[mi][2 * p + 1], af[mi], bfr[p][1], bfr[p][3]);
                }
        }
        __syncthreads();
    }

    // ------------------------------ epilogue ------------------------------
    const int tr = lane >> 2;
    const int tc = (lane & 3) * 2;
    const bool staged = (MODE == 1) || (MODE == 2 && bn >= 1024);
    if (staged) {
        float* st = (float*)sm;
#pragma unroll
        for (int mi = 0; mi < 4; mi++)
#pragma unroll
            for (int r2 = 0; r2 < 2; r2++) {
                const int ml = wm + mi * 16 + tr + r2 * 8;
#pragma unroll
                for (int nj = 0; nj < 4; nj++) {
                    const int nl = wn + nj * 8 + tc;
                    st[nl * 132 + ml]       = acc[mi][nj][r2 * 2 + 0] * alpha;
                    st[(nl + 1) * 132 + ml] = acc[mi][nj][r2 * 2 + 1] * alpha;
                }
            }
        __syncthreads();
        if (MODE == 1) {
            const long bzMN = (long)bz * M * N;
#pragma unroll
            for (int r = 0; r < 16; r++) {
                const int nl = wid * 16 + r;
                const int n = bn + nl;
                float bv = bias ? bias[n] : 0.f;
                float4 v = *(float4*)&st[nl * 132 + lane * 4];
                v.x += bv; v.y += bv; v.z += bv; v.w += bv;
                const long i0 = bzMN + (long)n * M + bm + lane * 4;
                if (R) {
                    float4 rv = *(const float4*)(R + i0);
                    v.x += rcoef * rv.x; v.y += rcoef * rv.y;
                    v.z += rcoef * rv.z; v.w += rcoef * rv.w;
                }
                if (Cf) *(float4*)(Cf + i0) = v;
                if (Cb) {
                    __half2 h0v = __floats2half2_rn(v.x, v.y);
                    __half2 h1v = __floats2half2_rn(v.z, v.w);
                    *(uint2*)(Cb + i0) = make_uint2(*(uint32_t*)&h0v, *(uint32_t*)&h1v);
                }
            }
        } else {
            // MODE 2, v part: write transposed into Cb2 (v^T per batch 512x1024)
#pragma unroll
            for (int r = 0; r < 16; r++) {
                const int nl = wid * 16 + r;
                const int vrow = bn - 1024 + nl;
                float4 v = *(float4*)&st[nl * 132 + lane * 4];
                __half2 h0v = __floats2half2_rn(v.x, v.y);
                __half2 h1v = __floats2half2_rn(v.z, v.w);
                const long i0 = (long)bz * 524288 + (long)vrow * 1024 + bm + lane * 4;
                *(uint2*)(Cb2 + i0) = make_uint2(*(uint32_t*)&h0v, *(uint32_t*)&h1v);
            }
        }
    } else {
        const long bzC = (long)bz * M * ldc;
        float gs0 = 0.f, gss0 = 0.f, gs1 = 0.f, gss1 = 0.f;
#pragma unroll
        for (int mi = 0; mi < 4; mi++) {
#pragma unroll
            for (int r2 = 0; r2 < 2; r2++) {
                const int m = bm + wm + mi * 16 + tr + r2 * 8;
                if (m >= M) continue;
                float rAcc = 0.f;
                float inv = 1.f;
                if (rdiv) inv = 1.f / rdiv[(long)bz * M + m];
#pragma unroll
                for (int nj = 0; nj < 4; nj++) {
                    const int n = bn + wn + nj * 8 + tc;
                    float v0 = acc[mi][nj][r2 * 2 + 0] * alpha;
                    float v1 = acc[mi][nj][r2 * 2 + 1] * alpha;
                    if (bias) { v0 += bias[n]; v1 += bias[n + 1]; }
                    if (rsum) {
                        v0 = __expf(v0); v1 = __expf(v1);
                        rAcc += v0 + v1;
                    }
                    v0 *= inv; v1 *= inv;
                    const long i0 = bzC + (long)m * ldc + n;
                    if (R) {
                        float2 rv = *(const float2*)(R + i0);
                        v0 += rcoef * rv.x; v1 += rcoef * rv.y;
                    }
                    if (MODE == 3) {
                        if (nj < 2) { gs0 += v0 + v1; gss0 += v0 * v0 + v1 * v1; }
                        else        { gs1 += v0 + v1; gss1 += v0 * v0 + v1 * v1; }
                    }
                    if (Cf) *(float2*)(Cf + i0) = make_float2(v0, v1);
                    if (Cb) {
                        __half2 hv = __floats2half2_rn(v0, v1);
                        *(uint32_t*)(Cb + i0) = *(uint32_t*)&hv;
                    }
                }
                if (rsum) {
                    rAcc += __shfl_xor_sync(0xffffffffu, rAcc, 1);
                    rAcc += __shfl_xor_sync(0xffffffffu, rAcc, 2);
                    if ((lane & 3) == 0)
                        atomicAdd(&rsum[(long)bz * M + m], rAcc);
                }
            }
        }
        if (MODE == 3) {
            // groups are warp-uniform: reduce across the warp, lane 0 commits.
            gs0  = warpSum(gs0);  gss0 = warpSum(gss0);
            gs1  = warpSum(gs1);  gss1 = warpSum(gss1);
            if (lane == 0) {
                const int g0 = (bn + wn) >> 4;
                atomicAdd(&gstats[((long)bz * 32 + g0) * 2],     gs0);
                atomicAdd(&gstats[((long)bz * 32 + g0) * 2 + 1], gss0);
                atomicAdd(&gstats[((long)bz * 32 + g0 + 1) * 2],     gs1);
                atomicAdd(&gstats[((long)bz * 32 + g0 + 1) * 2 + 1], gss1);
            }
        }
    }
#undef LOADC
}

template <int MODE>
static void gemm(const __half* A, long sA, int lda,
                 const __half* B, long sB, int ldb,
                 float* Cf, __half* Cb, __half* Cb2,
                 const float* bias, const float* R,
                 float rcoef, float alpha, int M, int N, int K, int ldc,
                 float* rsum, const float* rdiv, float* gstats) {
    cudaFuncSetAttribute(gemm_mma<MODE>, cudaFuncAttributeMaxDynamicSharedMemorySize, GSMEM);
    dim3 grid(N / 128, (M + 127) / 128, NB);
    gemm_mma<MODE><<<grid, 256, GSMEM>>>(A, sA, lda, B, sB, ldb, Cf, Cb, Cb2,
                                         bias, R, rcoef, alpha, M, N, K, ldc,
                                         rsum, rdiv, gstats);
}

// ===================== driver ================================================
extern "C" void kernel_launch(void* const* d_in, const int* in_sizes, int n_in,
                              void* d_out, int out_size) {
    const float* x      = (const float*)d_in[0];
    const float* ctx    = (const float*)d_in[1];
    const float* gn1_g  = (const float*)d_in[2];
    const float* gn1_b  = (const float*)d_in[3];
    const float* w_in   = (const float*)d_in[4];
    const float* b_in   = (const float*)d_in[5];
    const float* sa_wk  = (const float*)d_in[6];
    const float* sa_wq  = (const float*)d_in[7];
    const float* sa_wv  = (const float*)d_in[8];
    const float* sa_wp  = (const float*)d_in[9];
    const float* sa_gng = (const float*)d_in[10];
    const float* sa_gnb = (const float*)d_in[11];
    const float* ca_wq  = (const float*)d_in[12];
    const float* ca_wk  = (const float*)d_in[13];
    const float* ca_wv  = (const float*)d_in[14];
    const float* ca_wo  = (const float*)d_in[15];
    const float* ca_bo  = (const float*)d_in[16];
    const float* w_out  = (const float*)d_in[17];
    const float* b_out  = (const float*)d_in[18];
    float* out = (float*)d_out;

    float *h0, *h1, *kvc, *rs, *gst;
    __half *wh, *xnh, *hnh, *qkh, *qh, *vth, *oh, *h1h, *h2h, *ofh, *attnh;
    cudaGetSymbolAddress((void**)&h0,  g_h0);
    cudaGetSymbolAddress((void**)&h1,  g_h1);
    cudaGetSymbolAddress((void**)&kvc, g_kvc);
    cudaGetSymbolAddress((void**)&rs,  g_rsum);
    cudaGetSymbolAddress((void**)&gst, g_gst);
    cudaGetSymbolAddress((void**)&wh,  g_wh);
    cudaGetSymbolAddress((void**)&xnh, g_xnh);
    cudaGetSymbolAddress((void**)&hnh, g_hnh);
    cudaGetSymbolAddress((void**)&qkh, g_qkh);
    cudaGetSymbolAddress((void**)&qh,  g_qh);
    cudaGetSymbolAddress((void**)&vth, g_vth);
    cudaGetSymbolAddress((void**)&oh,  g_oh);
    cudaGetSymbolAddress((void**)&h1h, g_h1h);
    cudaGetSymbolAddress((void**)&h2h, g_h2h);
    cudaGetSymbolAddress((void**)&ofh, g_ofh);
    cudaGetSymbolAddress((void**)&attnh, g_attn);

    __half* wh_in   = wh;
    __half* wh_qkv  = wh + 131072;     // sa_wq | sa_wk | sa_wv contiguous [1536,512]
    __half* wh_sap  = wh + 917504;
    __half* wh_caq  = wh + 1179648;
    __half* wh_cakv = wh + 1441792;    // ca_wk | ca_wv [1024,768]
    __half* wh_cao  = wh + 2228224;
    __half* wh_out  = wh + 2490368;
    __half* ctx_h   = wh + 2621440;

    const float inv_sqrt_c = 0.044194173824159216f;   // 512^-0.5

    // 0. convert weights + ctx to fp16
    CvtSrc cs;
    cs.p[0] = w_in;  cs.p[1] = sa_wq; cs.p[2] = sa_wk; cs.p[3] = sa_wv;
    cs.p[4] = sa_wp; cs.p[5] = ca_wq; cs.p[6] = ca_wk; cs.p[7] = ca_wv;
    cs.p[8] = ca_wo; cs.p[9] = w_out; cs.p[10] = ctx;
    cvt_k<<<(int)((WH_TOTAL + 255) / 256), 256>>>(cs);

    // 1. GN1(x) -> xnh fp16 [b,n,c] (also zeroes rsum + gn2 stats)
    gn1_stats_k<<<NB * 32, 256>>>(x);
    gn1_apply_k<<<dim3(32, 8, NB), dim3(32, 8)>>>(x, gn1_g, gn1_b);
    // 2. conv_in (MODE 3): h0 = xn @ w_in^T + b_in; GN2 stats via reduced atomics
    gemm<3>(xnh, (long)HW * CIN, CIN, wh_in, 0, CIN, h0, nullptr, nullptr,
            b_in, nullptr, 0.f, 1.f, HW, INNER, CIN, INNER, nullptr, nullptr, gst);
    // 3. GN2 apply (single pass)
    gn2_apply_k<<<NB * 32, 256>>>(sa_gng, sa_gnb);
    // 4. merged q|k|v: N=1536; q|k -> qkh (ldc=1024), v -> vth transposed
    gemm<2>(hnh, (long)HW * INNER, INNER, wh_qkv, 0, INNER, nullptr, qkh, vth,
            nullptr, nullptr, 0.f, 1.f, HW, 1536, INNER, 1024, nullptr, nullptr, nullptr);
    // 5. attn_unnorm = exp(q @ k^T * c^-0.5); rowsums accumulated
    gemm<0>(qkh, (long)HW * 1024, 1024, qkh + 512, (long)HW * 1024, 1024,
            nullptr, attnh, nullptr, nullptr, nullptr, 0.f, inv_sqrt_c,
            HW, HW, INNER, HW, rs, nullptr, nullptr);
    // 6. o = (exp_attn @ v) / rowsum -> oh fp16
    gemm<0>(attnh, (long)HW * HW, HW, vth, (long)INNER * HW, HW,
            nullptr, oh, nullptr, nullptr, nullptr, 0.f, 1.f,
            HW, INNER, HW, INNER, nullptr, rs, nullptr);
    // 7. h1 = o @ wp^T + 2*h0 (fp32 + fp16 copies)
    gemm<0>(oh, (long)HW * INNER, INNER, wh_sap, 0, INNER, h1, h1h, nullptr,
            nullptr, h0, 2.f, 1.f, HW, INNER, INNER, INNER, nullptr, nullptr, nullptr);
    // 8. CA projections: q fp16, fused k|v fp32
    gemm<0>(h1h, (long)HW * INNER, INNER, wh_caq, 0, INNER, nullptr, qh, nullptr,
            nullptr, nullptr, 0.f, 1.f, HW, INNER, INNER, INNER, nullptr, nullptr, nullptr);
    gemm<0>(ctx_h, (long)CTXN * CTXD, CTXD, wh_cakv, 0, CTXD, kvc, nullptr, nullptr,
            nullptr, nullptr, 0.f, 1.f, CTXN, 1024, CTXD, 1024, nullptr, nullptr, nullptr);
    // 9. fused cross-attention (half2) -> ofh fp16
    ca_attn_k<<<dim3(NB * 8, 4), 256>>>();
    // 10. h2 = o @ ca_wo^T + ca_bo + h1 -> h2h fp16
    gemm<0>(ofh, (long)HW * INNER, INNER, wh_cao, 0, INNER, nullptr, h2h, nullptr,
            ca_bo, h1, 1.f, 1.f, HW, INNER, INNER, INNER, nullptr, nullptr, nullptr);
    // 11. out = h2 @ w_out^T + b_out + x (MODE 1 -> NCHW fp32, staged)
    gemm<1>(h2h, (long)HW * INNER, INNER, wh_out, 0, INNER, out, nullptr, nullptr,
            b_out, x, 1.f, 1.f, HW, CIN, INNER, CIN, nullptr, nullptr, nullptr);
}

// round 16
// speedup vs baseline: 1.1505x; 1.0119x over previous
#include <cuda_runtime.h>
#include <cuda_fp16.h>
#include <math.h>
#include <stdint.h>

#define NB    16
#define CIN   256
#define HW    1024
#define INNER 512
#define CTXN  77
#define CTXD  768
#define DH    64

// ===================== PTX helpers (sm_80-safe only) =========================
__device__ __forceinline__ uint32_t smem_to_u32(const void* p) {
    uint32_t a;
    asm("{ .reg .u64 t; cvta.to.shared.u64 t, %1; cvt.u32.u64 %0, t; }" : "=r"(a) : "l"(p));
    return a;
}
__device__ __forceinline__ void cp16(uint32_t dst, const void* src, bool valid) {
    int sz = valid ? 16 : 0;
    asm volatile("cp.async.cg.shared.global [%0], [%1], 16, %2;"
                 :: "r"(dst), "l"(src), "r"(sz) : "memory");
}
#define CP_COMMIT() asm volatile("cp.async.commit_group;" ::: "memory")
template <int N>
__device__ __forceinline__ void cp_wait() {
    asm volatile("cp.async.wait_group %0;" :: "n"(N) : "memory");
}
__device__ __forceinline__ void ldsm_x4(uint32_t* r, uint32_t addr) {
    asm volatile("ldmatrix.sync.aligned.m8n8.x4.shared.b16 {%0,%1,%2,%3}, [%4];"
        : "=r"(r[0]), "=r"(r[1]), "=r"(r[2]), "=r"(r[3]) : "r"(addr));
}
__device__ __forceinline__ void mma_f16(float* d, const uint32_t* a,
                                        uint32_t b0, uint32_t b1) {
    asm volatile(
        "mma.sync.aligned.m16n8k16.row.col.f32.f16.f16.f32 "
        "{%0,%1,%2,%3}, {%4,%5,%6,%7}, {%8,%9}, {%0,%1,%2,%3};"
        : "+f"(d[0]), "+f"(d[1]), "+f"(d[2]), "+f"(d[3])
        : "r"(a[0]), "r"(a[1]), "r"(a[2]), "r"(a[3]), "r"(b0), "r"(b1));
}

// ===================== scratch (device globals) ==============================
#define WH_TOTAL 3567616L
__device__ __align__(16) __half g_wh[WH_TOTAL];            // fp16 weights + ctx
__device__ __align__(16) float g_h0 [NB * HW * INNER];     // conv_in out (fp32)
__device__ __align__(16) float g_h1 [NB * HW * INNER];     // after SA (fp32)
__device__ __align__(16) float g_kvc[NB * CTXN * 1024];
__device__ __align__(16) float g_rsum[NB * HW];            // softmax row sums
__device__ __align__(16) float g_gst[NB * 32 * 2];         // GN2 group s/ss
__device__ float g_stats[NB * 32 * 2];
__device__ __align__(16) __half g_xnh [NB * HW * CIN];
__device__ __align__(16) __half g_hnh [NB * HW * INNER];
__device__ __align__(16) __half g_qkh [NB * HW * 1024];    // q|k merged
__device__ __align__(16) __half g_qh  [NB * HW * INNER];   // CA q
__device__ __align__(16) __half g_vth [NB * HW * INNER];   // v^T
__device__ __align__(16) __half g_oh  [NB * HW * INNER];   // SA attn out
__device__ __align__(16) __half g_h1h [NB * HW * INNER];
__device__ __align__(16) __half g_h2h [NB * HW * INNER];
__device__ __align__(16) __half g_ofh [NB * HW * INNER];   // CA attn out
__device__ __align__(16) __half g_attn[(long)NB * HW * HW];

// ===================== reductions ============================================
__device__ __forceinline__ float warpSum(float v) {
#pragma unroll
    for (int o = 16; o; o >>= 1) v += __shfl_xor_sync(0xffffffffu, v, o);
    return v;
}
__device__ float blockSum(float v) {
    __shared__ float sm[8];
    int t = threadIdx.x;
    v = warpSum(v);
    if ((t & 31) == 0) sm[t >> 5] = v;
    __syncthreads();
    if (t < 32) {
        float w = (t < 8) ? sm[t] : 0.f;
        w = warpSum(w);
        if (t == 0) sm[0] = w;
    }
    __syncthreads();
    float r = sm[0];
    __syncthreads();
    return r;
}

// ===================== conversions ===========================================
struct CvtSrc { const float* p[11]; };
__global__ void cvt_k(CvtSrc a) {
    long i = (long)blockIdx.x * 256 + threadIdx.x;
    if (i >= WH_TOTAL) return;
    const long ends[11] = {131072, 393216, 655360, 917504, 1179648, 1441792,
                           1835008, 2228224, 2490368, 2621440, 3567616};
    int s = 0; long off = 0;
#pragma unroll
    for (int k = 0; k < 11; k++) {
        if (i >= ends[k]) { s = k + 1; off = ends[k]; }
    }
    g_wh[i] = __float2half_rn(a.p[s][i - off]);
}

// ===================== GroupNorm 1 ===========================================
__global__ void gn1_stats_k(const float* __restrict__ x) {
    int bg = blockIdx.x;
    // zero per-replay accumulators (runs before all atomic producers)
    if (threadIdx.x < 32) g_rsum[bg * 32 + threadIdx.x] = 0.f;
    if (threadIdx.x < 2)  g_gst[bg * 2 + threadIdx.x] = 0.f;
    const float* p = x + (long)bg * 8192;
    float s = 0.f, ss = 0.f;
    for (int i = threadIdx.x; i < 2048; i += 256) {
        float4 v = ((const float4*)p)[i];
        s += v.x + v.y + v.z + v.w;
        ss += v.x * v.x + v.y * v.y + v.z * v.z + v.w * v.w;
    }
    s = blockSum(s); ss = blockSum(ss);
    if (threadIdx.x == 0) {
        float mean = s * (1.f / 8192.f);
        float var  = ss * (1.f / 8192.f) - mean * mean;
        g_stats[bg * 2]     = mean;
        g_stats[bg * 2 + 1] = rsqrtf(var + 1e-5f);
    }
}
// tiled transpose + normalize: x [b][c][n] fp32 -> xnh [b][n][c] fp16
__global__ void gn1_apply_k(const float* __restrict__ x,
                            const float* __restrict__ gam,
                            const float* __restrict__ bet) {
    __shared__ float t[32][33];
    int b = blockIdx.z;
    int c0 = blockIdx.y * 32;
    int n0 = blockIdx.x * 32;
    int tx = threadIdx.x, ty = threadIdx.y;
#pragma unroll
    for (int i = 0; i < 4; i++) {
        int c = c0 + ty + i * 8;
        float v = x[((long)(b * 256 + c) << 10) + n0 + tx];
        int sg = (b << 5) | (c >> 3);
        t[ty + i * 8][tx] = (v - g_stats[sg * 2]) * g_stats[sg * 2 + 1] * gam[c] + bet[c];
    }
    __syncthreads();
#pragma unroll
    for (int i = 0; i < 4; i++) {
        int n = n0 + ty + i * 8;
        g_xnh[((long)(b * 1024 + n) << 8) + c0 + tx] = __float2half_rn(t[tx][ty + i * 8]);
    }
}

// ===================== GroupNorm 2 apply (stats fused into conv_in) ==========
__global__ void gn2_apply_k(const float* __restrict__ gg,
                            const float* __restrict__ gb) {
    int b = blockIdx.x >> 5, g = blockIdx.x & 31;
    float s  = g_gst[(b * 32 + g) * 2];
    float ss = g_gst[(b * 32 + g) * 2 + 1];
    float mean = s * (1.f / 16384.f);
    float rstd = rsqrtf(ss * (1.f / 16384.f) - mean * mean + 1e-5f);
    const float4* p = (const float4*)(g_h0 + (long)b * HW * INNER + g * 16);
    __half* q = g_hnh + (long)b * HW * INNER + g * 16;
    for (int i = threadIdx.x; i < HW * 4; i += 256) {
        int n = i >> 2, j = i & 3;
        int c = g * 16 + j * 4;
        float4 v = p[n * 128 + j];
        __half2 h0 = __floats2half2_rn(
            (v.x - mean) * rstd * gg[c] + gb[c],
            (v.y - mean) * rstd * gg[c + 1] + gb[c + 1]);
        __half2 h1 = __floats2half2_rn(
            (v.z - mean) * rstd * gg[c + 2] + gb[c + 2],
            (v.w - mean) * rstd * gg[c + 3] + gb[c + 3]);
        *(uint2*)(q + n * INNER + j * 4) = make_uint2(
            *(uint32_t*)&h0, *(uint32_t*)&h1);
    }
}

// ===================== fused cross-attention (half2 math) ====================
__global__ void __launch_bounds__(256) ca_attn_k() {
    __shared__ __half2 Ks[CTXN][DH / 2];
    __shared__ __half2 Vs[CTXN][DH / 2];
    int b = blockIdx.x >> 3, h = blockIdx.x & 7;
    const float2* kp = (const float2*)(g_kvc + (long)b * CTXN * 1024 + h * DH);
    const float2* vp = (const float2*)(g_kvc + (long)b * CTXN * 1024 + 512 + h * DH);
    for (int i = threadIdx.x; i < CTXN * 32; i += 256) {
        int j = i >> 5, d = i & 31;
        float2 kf = kp[j * 512 + d];
        float2 vf = vp[j * 512 + d];
        Ks[j][d] = __floats2half2_rn(kf.x, kf.y);
        Vs[j][d] = __floats2half2_rn(vf.x, vf.y);
    }
    __syncthreads();
    int i = blockIdx.y * 256 + threadIdx.x;
    const __half2* qp = (const __half2*)(g_qh + ((long)(b * HW + i)) * INNER + h * DH);
    __half2 qv[32];
    uint4* qv4 = (uint4*)qv;
#pragma unroll
    for (int d = 0; d < 8; d++) qv4[d] = ((const uint4*)qp)[d];

    float l = 0.f;
    __half2 acc[32];
    const __half2 z2 = __float2half2_rn(0.f);
#pragma unroll
    for (int d = 0; d < 32; d++) acc[d] = z2;
    for (int j = 0; j < CTXN; j++) {
        __half2 d2 = __hmul2(qv[0], Ks[j][0]);
#pragma unroll
        for (int d = 1; d < 32; d++) d2 = __hfma2(qv[d], Ks[j][d], d2);
        float s = (__low2float(d2) + __high2float(d2)) * 0.125f;
        float e = __expf(s);
        l += e;
        __half2 e2 = __float2half2_rn(e);
#pragma unroll
        for (int d = 0; d < 32; d++) acc[d] = __hfma2(e2, Vs[j][d], acc[d]);
    }
    float inv = 1.f / l;
    __half* op = g_ofh + ((long)(b * HW + i)) * INNER + h * DH;
#pragma unroll
    for (int d = 0; d < 32; d += 4) {
        __half2 pk[4];
#pragma unroll
        for (int e = 0; e < 4; e++) {
            float2 a = __half22float2(acc[d + e]);
            pk[e] = __floats2half2_rn(a.x * inv, a.y * inv);
        }
        *(uint4*)(op + d * 2) = *(uint4*)pk;
    }
}

// ===================== fp16 mma.sync GEMM (template modes) ===================
// MODE 0: C row-major (stride ldc); optional rsum/rdiv (fused softmax), bias, R.
// MODE 1: C transposed [N, M] per batch (staged, coalesced), Cf/Cb.
// MODE 2: merged qkv — bn<1024: Cb row-major (ldc=1024); bn>=1024: v^T into
//         Cb2 (per-batch 512x1024), staged transpose.
// MODE 3: MODE 0 + GN2 group stats via warp-reduced atomics (contention-free).
// CTA 128x128, 8 warps (2x4, 64x32), BK=64, 3 stages x 32KB, 2 CTAs/SM.
#define STAGE_B 32768
#define GSMEM   98304

__device__ __forceinline__ void frag_load(
    uint32_t aT, uint32_t bT, int wm, int wn, int lane, int kk,
    uint32_t af[4][4], uint32_t bfr[2][4]) {
    const int r0 = lane & 15;
    const int uu = kk * 2 + (lane >> 4);
#pragma unroll
    for (int mi = 0; mi < 4; mi++) {
        int r = wm + mi * 16 + r0;
        ldsm_x4(af[mi], aT + r * 128 + ((uu ^ (r & 7)) << 4));
    }
#pragma unroll
    for (int p = 0; p < 2; p++) {
        int r = wn + p * 16 + r0;
        ldsm_x4(bfr[p], bT + r * 128 + ((uu ^ (r & 7)) << 4));
    }
}

template <int MODE>
__global__ void __launch_bounds__(256, 2) gemm_mma(
    const __half* __restrict__ A_, long sA, int lda,
    const __half* __restrict__ B_, long sB, int ldb,
    float* __restrict__ Cf, __half* __restrict__ Cb, __half* __restrict__ Cb2,
    const float* __restrict__ bias, const float* __restrict__ R,
    float rcoef, float alpha, int M, int N, int K, int ldc,
    float* __restrict__ rsum, const float* __restrict__ rdiv,
    float* __restrict__ gstats) {
    extern __shared__ __align__(128) char sm[];
    const uint32_t sb = smem_to_u32(sm);
    const int tid  = threadIdx.x;
    const int lane = tid & 31;
    const int wid  = tid >> 5;
    const int bz = blockIdx.z;
    const int bm = blockIdx.y * 128;
    const int bn = blockIdx.x * 128;
    const int wm = (wid >> 2) * 64;
    const int wn = (wid & 3) * 32;
    const __half* Ab = A_ + (long)bz * sA;
    const __half* Bb = B_ + (long)bz * sB;

    float acc[4][4][4];
#pragma unroll
    for (int i = 0; i < 4; i++)
#pragma unroll
        for (int j = 0; j < 4; j++)
#pragma unroll
            for (int e = 0; e < 4; e++) acc[i][j][e] = 0.f;

    const int lrow = tid >> 1;
    const int lu0  = (tid & 1) * 4;
    const bool aValid = (bm + lrow) < M;
    const long aOff = aValid ? (long)(bm + lrow) * lda : 0;
    const long bOff = (long)(bn + lrow) * ldb;
    const int nIter = K >> 6;

#define LOADC(i, s) do {                                                        \
    uint32_t dA = sb + (s) * STAGE_B + lrow * 128;                              \
    uint32_t dB = dA + 16384;                                                   \
    const __half* gA = Ab + aOff + ((long)(i) << 6);                            \
    const __half* gB = Bb + bOff + ((long)(i) << 6);                            \
    _Pragma("unroll")                                                           \
    for (int j = 0; j < 4; j++) {                                               \
        int u = lu0 + j;                                                        \
        uint32_t so = (uint32_t)((u ^ (lrow & 7)) << 4);                        \
        cp16(dA + so, gA + u * 8, aValid);                                      \
        cp16(dB + so, gB + u * 8, true);                                        \
    }                                                                           \
} while (0)

    LOADC(0, 0); CP_COMMIT();
    if (1 < nIter) { LOADC(1, 1); }
    CP_COMMIT();

    uint32_t af[4][4], bfr[2][4];

    for (int it = 0; it < nIter; it++) {
        const int s = it % 3;
        if (it + 1 < nIter) cp_wait<1>(); else cp_wait<0>();
        __syncthreads();
        if (it + 2 < nIter) { LOADC(it + 2, (it + 2) % 3); CP_COMMIT(); }

        const uint32_t aT = sb + s * STAGE_B;
        const uint32_t bT = aT + 16384;
#pragma unroll
        for (int kk = 0; kk < 4; kk++) {
            frag_load(aT, bT, wm, wn, lane, kk, af, bfr);
#pragma unroll
            for (int mi = 0; mi < 4; mi++)
#pragma unroll
                for (int p = 0; p < 2; p++) {
                    mma_f16(acc[mi][2 * p],     af[mi], bfr[p][0], bfr[p][2]);
                    mma_f16(acc[mi][2 * p + 1], af[mi], bfr[p][1], bfr[p][3]);
                }
        }
        __syncthreads();
    }

    // ------------------------------ epilogue ------------------------------
    const int tr = lane >> 2;
    const int tc = (lane & 3) * 2;
    const bool staged = (MODE == 1) || (MODE == 2 && bn >= 1024);
    if (staged) {
        float* st = (float*)sm;
#pragma unroll
        for (int mi = 0; mi < 4; mi++)
#pragma unroll
            for (int r2 = 0; r2 < 2; r2++) {
                const int ml = wm + mi * 16 + tr + r2 * 8;
#pragma unroll
                for (int nj = 0; nj < 4; nj++) {
                    const int nl = wn + nj * 8 + tc;
                    st[nl * 132 + ml]       = acc[mi][nj][r2 * 2 + 0] * alpha;
                    st[(nl + 1) * 132 + ml] = acc[mi][nj][r2 * 2 + 1] * alpha;
                }
            }
        __syncthreads();
        if (MODE == 1) {
            const long bzMN = (long)bz * M * N;
#pragma unroll
            for (int r = 0; r < 16; r++) {
                const int nl = wid * 16 + r;
                const int n = bn + nl;
                float bv = bias ? bias[n] : 0.f;
                float4 v = *(float4*)&st[nl * 132 + lane * 4];
                v.x += bv; v.y += bv; v.z += bv; v.w += bv;
                const long i0 = bzMN + (long)n * M + bm + lane * 4;
                if (R) {
                    float4 rv = *(const float4*)(R + i0);
                    v.x += rcoef * rv.x; v.y += rcoef * rv.y;
                    v.z += rcoef * rv.z; v.w += rcoef * rv.w;
                }
                if (Cf) *(float4*)(Cf + i0) = v;
                if (Cb) {
                    __half2 h0v = __floats2half2_rn(v.x, v.y);
                    __half2 h1v = __floats2half2_rn(v.z, v.w);
                    *(uint2*)(Cb + i0) = make_uint2(*(uint32_t*)&h0v, *(uint32_t*)&h1v);
                }
            }
        } else {
            // MODE 2, v part: write transposed into Cb2 (v^T per batch 512x1024)
#pragma unroll
            for (int r = 0; r < 16; r++) {
                const int nl = wid * 16 + r;
                const int vrow = bn - 1024 + nl;
                float4 v = *(float4*)&st[nl * 132 + lane * 4];
                __half2 h0v = __floats2half2_rn(v.x, v.y);
                __half2 h1v = __floats2half2_rn(v.z, v.w);
                const long i0 = (long)bz * 524288 + (long)vrow * 1024 + bm + lane * 4;
                *(uint2*)(Cb2 + i0) = make_uint2(*(uint32_t*)&h0v, *(uint32_t*)&h1v);
            }
        }
    } else {
        const long bzC = (long)bz * M * ldc;
        float gs0 = 0.f, gss0 = 0.f, gs1 = 0.f, gss1 = 0.f;
#pragma unroll
        for (int mi = 0; mi < 4; mi++) {
#pragma unroll
            for (int r2 = 0; r2 < 2; r2++) {
                const int m = bm + wm + mi * 16 + tr + r2 * 8;
                if (m >= M) continue;
                float rAcc = 0.f;
                float inv = 1.f;
                if (rdiv) inv = 1.f / rdiv[(long)bz * M + m];
#pragma unroll
                for (int nj = 0; nj < 4; nj++) {
                    const int n = bn + wn + nj * 8 + tc;
                    float v0 = acc[mi][nj][r2 * 2 + 0] * alpha;
                    float v1 = acc[mi][nj][r2 * 2 + 1] * alpha;
                    if (bias) { v0 += bias[n]; v1 += bias[n + 1]; }
                    if (rsum) {
                        v0 = __expf(v0); v1 = __expf(v1);
                        rAcc += v0 + v1;
                    }
                    v0 *= inv; v1 *= inv;
                    const long i0 = bzC + (long)m * ldc + n;
                    if (R) {
                        float2 rv = *(const float2*)(R + i0);
                        v0 += rcoef * rv.x; v1 += rcoef * rv.y;
                    }
                    if (MODE == 3) {
                        if (nj < 2) { gs0 += v0 + v1; gss0 += v0 * v0 + v1 * v1; }
                        else        { gs1 += v0 + v1; gss1 += v0 * v0 + v1 * v1; }
                    }
                    if (Cf) *(float2*)(Cf + i0) = make_float2(v0, v1);
                    if (Cb) {
                        __half2 hv = __floats2half2_rn(v0, v1);
                        *(uint32_t*)(Cb + i0) = *(uint32_t*)&hv;
                    }
                }
                if (rsum) {
                    rAcc += __shfl_xor_sync(0xffffffffu, rAcc, 1);
                    rAcc += __shfl_xor_sync(0xffffffffu, rAcc, 2);
                    if ((lane & 3) == 0)
                        atomicAdd(&rsum[(long)bz * M + m], rAcc);
                }
            }
        }
        if (MODE == 3) {
            gs0  = warpSum(gs0);  gss0 = warpSum(gss0);
            gs1  = warpSum(gs1);  gss1 = warpSum(gss1);
            if (lane == 0) {
                const int g0 = (bn + wn) >> 4;
                atomicAdd(&gstats[((long)bz * 32 + g0) * 2],     gs0);
                atomicAdd(&gstats[((long)bz * 32 + g0) * 2 + 1], gss0);
                atomicAdd(&gstats[((long)bz * 32 + g0 + 1) * 2],     gs1);
                atomicAdd(&gstats[((long)bz * 32 + g0 + 1) * 2 + 1], gss1);
            }
        }
    }
#undef LOADC
}

template <int MODE>
static void gemm(cudaStream_t st,
                 const __half* A, long sA, int lda,
                 const __half* B, long sB, int ldb,
                 float* Cf, __half* Cb, __half* Cb2,
                 const float* bias, const float* R,
                 float rcoef, float alpha, int M, int N, int K, int ldc,
                 float* rsum, const float* rdiv, float* gstats) {
    cudaFuncSetAttribute(gemm_mma<MODE>, cudaFuncAttributeMaxDynamicSharedMemorySize, GSMEM);
    dim3 grid(N / 128, (M + 127) / 128, NB);
    gemm_mma<MODE><<<grid, 256, GSMEM, st>>>(A, sA, lda, B, sB, ldb, Cf, Cb, Cb2,
                                             bias, R, rcoef, alpha, M, N, K, ldc,
                                             rsum, rdiv, gstats);
}

// ===================== driver ================================================
extern "C" void kernel_launch(void* const* d_in, const int* in_sizes, int n_in,
                              void* d_out, int out_size) {
    const float* x      = (const float*)d_in[0];
    const float* ctx    = (const float*)d_in[1];
    const float* gn1_g  = (const float*)d_in[2];
    const float* gn1_b  = (const float*)d_in[3];
    const float* w_in   = (const float*)d_in[4];
    const float* b_in   = (const float*)d_in[5];
    const float* sa_wk  = (const float*)d_in[6];
    const float* sa_wq  = (const float*)d_in[7];
    const float* sa_wv  = (const float*)d_in[8];
    const float* sa_wp  = (const float*)d_in[9];
    const float* sa_gng = (const float*)d_in[10];
    const float* sa_gnb = (const float*)d_in[11];
    const float* ca_wq  = (const float*)d_in[12];
    const float* ca_wk  = (const float*)d_in[13];
    const float* ca_wv  = (const float*)d_in[14];
    const float* ca_wo  = (const float*)d_in[15];
    const float* ca_bo  = (const float*)d_in[16];
    const float* w_out  = (const float*)d_in[17];
    const float* b_out  = (const float*)d_in[18];
    float* out = (float*)d_out;

    // one-time host-side resources (created on the uncaptured correctness call)
    static cudaStream_t s_side = nullptr;
    static cudaEvent_t  s_evFork = nullptr, s_evCvt = nullptr, s_evKV = nullptr;
    if (!s_side) {
        cudaStreamCreateWithFlags(&s_side, cudaStreamNonBlocking);
        cudaEventCreateWithFlags(&s_evFork, cudaEventDisableTiming);
        cudaEventCreateWithFlags(&s_evCvt,  cudaEventDisableTiming);
        cudaEventCreateWithFlags(&s_evKV,   cudaEventDisableTiming);
    }
    cudaStream_t main = 0;

    float *h0, *h1, *kvc, *rs, *gst;
    __half *wh, *xnh, *hnh, *qkh, *qh, *vth, *oh, *h1h, *h2h, *ofh, *attnh;
    cudaGetSymbolAddress((void**)&h0,  g_h0);
    cudaGetSymbolAddress((void**)&h1,  g_h1);
    cudaGetSymbolAddress((void**)&kvc, g_kvc);
    cudaGetSymbolAddress((void**)&rs,  g_rsum);
    cudaGetSymbolAddress((void**)&gst, g_gst);
    cudaGetSymbolAddress((void**)&wh,  g_wh);
    cudaGetSymbolAddress((void**)&xnh, g_xnh);
    cudaGetSymbolAddress((void**)&hnh, g_hnh);
    cudaGetSymbolAddress((void**)&qkh, g_qkh);
    cudaGetSymbolAddress((void**)&qh,  g_qh);
    cudaGetSymbolAddress((void**)&vth, g_vth);
    cudaGetSymbolAddress((void**)&oh,  g_oh);
    cudaGetSymbolAddress((void**)&h1h, g_h1h);
    cudaGetSymbolAddress((void**)&h2h, g_h2h);
    cudaGetSymbolAddress((void**)&ofh, g_ofh);
    cudaGetSymbolAddress((void**)&attnh, g_attn);

    __half* wh_in   = wh;
    __half* wh_qkv  = wh + 131072;     // sa_wq | sa_wk | sa_wv contiguous [1536,512]
    __half* wh_sap  = wh + 917504;
    __half* wh_caq  = wh + 1179648;
    __half* wh_cakv = wh + 1441792;    // ca_wk | ca_wv [1024,768]
    __half* wh_cao  = wh + 2228224;
    __half* wh_out  = wh + 2490368;
    __half* ctx_h   = wh + 2621440;

    const float inv_sqrt_c = 0.044194173824159216f;   // 512^-0.5

    CvtSrc cs;
    cs.p[0] = w_in;  cs.p[1] = sa_wq; cs.p[2] = sa_wk; cs.p[3] = sa_wv;
    cs.p[4] = sa_wp; cs.p[5] = ca_wq; cs.p[6] = ca_wk; cs.p[7] = ca_wv;
    cs.p[8] = ca_wo; cs.p[9] = w_out; cs.p[10] = ctx;

    // ---- fork side branch off the capture stream ----
    cudaEventRecord(s_evFork, main);
    cudaStreamWaitEvent(s_side, s_evFork, 0);
    // side: weight/ctx conversion, then CA k|v projection (not needed till step 9)
    cvt_k<<<(int)((WH_TOTAL + 255) / 256), 256, 0, s_side>>>(cs);
    cudaEventRecord(s_evCvt, s_side);
    gemm<0>(s_side, ctx_h, (long)CTXN * CTXD, CTXD, wh_cakv, 0, CTXD,
            kvc, nullptr, nullptr, nullptr, nullptr, 0.f, 1.f,
            CTXN, 1024, CTXD, 1024, nullptr, nullptr, nullptr);
    cudaEventRecord(s_evKV, s_side);

    // main: GN1 (independent of cvt) — also zeroes rsum/gst
    gn1_stats_k<<<NB * 32, 256, 0, main>>>(x);
    gn1_apply_k<<<dim3(32, 8, NB), dim3(32, 8), 0, main>>>(x, gn1_g, gn1_b);
    // conv_in needs fp16 weights: join with cvt
    cudaStreamWaitEvent(main, s_evCvt, 0);
    // conv_in (MODE 3): h0 = xn @ w_in^T + b_in; GN2 stats via reduced atomics
    gemm<3>(main, xnh, (long)HW * CIN, CIN, wh_in, 0, CIN, h0, nullptr, nullptr,
            b_in, nullptr, 0.f, 1.f, HW, INNER, CIN, INNER, nullptr, nullptr, gst);
    // GN2 apply (single pass)
    gn2_apply_k<<<NB * 32, 256, 0, main>>>(sa_gng, sa_gnb);
    // merged q|k|v: N=1536; q|k -> qkh (ldc=1024), v -> vth transposed
    gemm<2>(main, hnh, (long)HW * INNER, INNER, wh_qkv, 0, INNER, nullptr, qkh, vth,
            nullptr, nullptr, 0.f, 1.f, HW, 1536, INNER, 1024, nullptr, nullptr, nullptr);
    // attn_unnorm = exp(q @ k^T * c^-0.5); rowsums accumulated
    gemm<0>(main, qkh, (long)HW * 1024, 1024, qkh + 512, (long)HW * 1024, 1024,
            nullptr, attnh, nullptr, nullptr, nullptr, 0.f, inv_sqrt_c,
            HW, HW, INNER, HW, rs, nullptr, nullptr);
    // o = (exp_attn @ v) / rowsum -> oh fp16
    gemm<0>(main, attnh, (long)HW * HW, HW, vth, (long)INNER * HW, HW,
            nullptr, oh, nullptr, nullptr, nullptr, 0.f, 1.f,
            HW, INNER, HW, INNER, nullptr, rs, nullptr);
    // h1 = o @ wp^T + 2*h0 (fp32 + fp16 copies)
    gemm<0>(main, oh, (long)HW * INNER, INNER, wh_sap, 0, INNER, h1, h1h, nullptr,
            nullptr, h0, 2.f, 1.f, HW, INNER, INNER, INNER, nullptr, nullptr, nullptr);
    // CA q projection
    gemm<0>(main, h1h, (long)HW * INNER, INNER, wh_caq, 0, INNER, nullptr, qh, nullptr,
            nullptr, nullptr, 0.f, 1.f, HW, INNER, INNER, INNER, nullptr, nullptr, nullptr);
    // join side branch (kvc ready) before cross-attention
    cudaStreamWaitEvent(main, s_evKV, 0);
    // fused cross-attention (half2) -> ofh fp16
    ca_attn_k<<<dim3(NB * 8, 4), 256, 0, main>>>();
    // h2 = o @ ca_wo^T + ca_bo + h1 -> h2h fp16
    gemm<0>(main, ofh, (long)HW * INNER, INNER, wh_cao, 0, INNER, nullptr, h2h, nullptr,
            ca_bo, h1, 1.f, 1.f, HW, INNER, INNER, INNER, nullptr, nullptr, nullptr);
    // out = h2 @ w_out^T + b_out + x (MODE 1 -> NCHW fp32, staged)
    gemm<1>(main, h2h, (long)HW * INNER, INNER, wh_out, 0, INNER, out, nullptr, nullptr,
            b_out, x, 1.f, 1.f, HW, CIN, INNER, CIN, nullptr, nullptr, nullptr);
}

// round 17
// speedup vs baseline: 1.3113x; 1.1398x over previous
#include <cuda_runtime.h>
#include <cuda_fp16.h>
#include <math.h>
#include <stdint.h>

#define NB    16
#define NBH   8
#define CIN   256
#define HW    1024
#define INNER 512
#define CTXN  77
#define CTXD  768
#define DH    64

// ===================== PTX helpers (sm_80-safe only) =========================
__device__ __forceinline__ uint32_t smem_to_u32(const void* p) {
    uint32_t a;
    asm("{ .reg .u64 t; cvta.to.shared.u64 t, %1; cvt.u32.u64 %0, t; }" : "=r"(a) : "l"(p));
    return a;
}
__device__ __forceinline__ void cp16(uint32_t dst, const void* src, bool valid) {
    int sz = valid ? 16 : 0;
    asm volatile("cp.async.cg.shared.global [%0], [%1], 16, %2;"
                 :: "r"(dst), "l"(src), "r"(sz) : "memory");
}
#define CP_COMMIT() asm volatile("cp.async.commit_group;" ::: "memory")
template <int N>
__device__ __forceinline__ void cp_wait() {
    asm volatile("cp.async.wait_group %0;" :: "n"(N) : "memory");
}
__device__ __forceinline__ void ldsm_x4(uint32_t* r, uint32_t addr) {
    asm volatile("ldmatrix.sync.aligned.m8n8.x4.shared.b16 {%0,%1,%2,%3}, [%4];"
        : "=r"(r[0]), "=r"(r[1]), "=r"(r[2]), "=r"(r[3]) : "r"(addr));
}
__device__ __forceinline__ void mma_f16(float* d, const uint32_t* a,
                                        uint32_t b0, uint32_t b1) {
    asm volatile(
        "mma.sync.aligned.m16n8k16.row.col.f32.f16.f16.f32 "
        "{%0,%1,%2,%3}, {%4,%5,%6,%7}, {%8,%9}, {%0,%1,%2,%3};"
        : "+f"(d[0]), "+f"(d[1]), "+f"(d[2]), "+f"(d[3])
        : "r"(a[0]), "r"(a[1]), "r"(a[2]), "r"(a[3]), "r"(b0), "r"(b1));
}

// ===================== scratch (device globals) ==============================
#define WH_TOTAL 3567616L
__device__ __align__(16) __half g_wh[WH_TOTAL];            // fp16 weights + ctx
__device__ __align__(16) float g_h0 [NB * HW * INNER];     // conv_in out (fp32)
__device__ __align__(16) float g_h1 [NB * HW * INNER];     // after SA (fp32)
__device__ __align__(16) float g_kvc[NB * CTXN * 1024];
__device__ __align__(16) float g_rsum[NB * HW];            // softmax row sums
__device__ __align__(16) float g_gst[NB * 32 * 2];         // GN2 group s/ss
__device__ float g_stats[NB * 32 * 2];
__device__ __align__(16) __half g_xnh [NB * HW * CIN];
__device__ __align__(16) __half g_hnh [NB * HW * INNER];
__device__ __align__(16) __half g_qkh [NB * HW * 1024];    // q|k merged
__device__ __align__(16) __half g_qh  [NB * HW * INNER];   // CA q
__device__ __align__(16) __half g_vth [NB * HW * INNER];   // v^T
__device__ __align__(16) __half g_oh  [NB * HW * INNER];   // SA attn out
__device__ __align__(16) __half g_h1h [NB * HW * INNER];
__device__ __align__(16) __half g_h2h [NB * HW * INNER];
__device__ __align__(16) __half g_ofh [NB * HW * INNER];   // CA attn out
__device__ __align__(16) __half g_attn[(long)NB * HW * HW];

// ===================== reductions ============================================
__device__ __forceinline__ float warpSum(float v) {
#pragma unroll
    for (int o = 16; o; o >>= 1) v += __shfl_xor_sync(0xffffffffu, v, o);
    return v;
}
__device__ float blockSum(float v) {
    __shared__ float sm[8];
    int t = threadIdx.x;
    v = warpSum(v);
    if ((t & 31) == 0) sm[t >> 5] = v;
    __syncthreads();
    if (t < 32) {
        float w = (t < 8) ? sm[t] : 0.f;
        w = warpSum(w);
        if (t == 0) sm[0] = w;
    }
    __syncthreads();
    float r = sm[0];
    __syncthreads();
    return r;
}

// ===================== conversions ===========================================
struct CvtSrc { const float* p[11]; };
__global__ void cvt_k(CvtSrc a) {
    long i = (long)blockIdx.x * 256 + threadIdx.x;
    if (i >= WH_TOTAL) return;
    const long ends[11] = {131072, 393216, 655360, 917504, 1179648, 1441792,
                           1835008, 2228224, 2490368, 2621440, 3567616};
    int s = 0; long off = 0;
#pragma unroll
    for (int k = 0; k < 11; k++) {
        if (i >= ends[k]) { s = k + 1; off = ends[k]; }
    }
    g_wh[i] = __float2half_rn(a.p[s][i - off]);
}

// ===================== GroupNorm 1 (batch-offset b0) =========================
__global__ void gn1_stats_k(const float* __restrict__ x, int b0) {
    int bg = b0 * 32 + blockIdx.x;
    if (threadIdx.x < 32) g_rsum[bg * 32 + threadIdx.x] = 0.f;
    if (threadIdx.x < 2)  g_gst[bg * 2 + threadIdx.x] = 0.f;
    const float* p = x + (long)bg * 8192;
    float s = 0.f, ss = 0.f;
    for (int i = threadIdx.x; i < 2048; i += 256) {
        float4 v = ((const float4*)p)[i];
        s += v.x + v.y + v.z + v.w;
        ss += v.x * v.x + v.y * v.y + v.z * v.z + v.w * v.w;
    }
    s = blockSum(s); ss = blockSum(ss);
    if (threadIdx.x == 0) {
        float mean = s * (1.f / 8192.f);
        float var  = ss * (1.f / 8192.f) - mean * mean;
        g_stats[bg * 2]     = mean;
        g_stats[bg * 2 + 1] = rsqrtf(var + 1e-5f);
    }
}
__global__ void gn1_apply_k(const float* __restrict__ x,
                            const float* __restrict__ gam,
                            const float* __restrict__ bet, int b0) {
    __shared__ float t[32][33];
    int b = b0 + blockIdx.z;
    int c0 = blockIdx.y * 32;
    int n0 = blockIdx.x * 32;
    int tx = threadIdx.x, ty = threadIdx.y;
#pragma unroll
    for (int i = 0; i < 4; i++) {
        int c = c0 + ty + i * 8;
        float v = x[((long)(b * 256 + c) << 10) + n0 + tx];
        int sg = (b << 5) | (c >> 3);
        t[ty + i * 8][tx] = (v - g_stats[sg * 2]) * g_stats[sg * 2 + 1] * gam[c] + bet[c];
    }
    __syncthreads();
#pragma unroll
    for (int i = 0; i < 4; i++) {
        int n = n0 + ty + i * 8;
        g_xnh[((long)(b * 1024 + n) << 8) + c0 + tx] = __float2half_rn(t[tx][ty + i * 8]);
    }
}

// ===================== GroupNorm 2 apply (stats from conv_in MODE 3) =========
__global__ void gn2_apply_k(const float* __restrict__ gg,
                            const float* __restrict__ gb, int b0) {
    int b = b0 + (blockIdx.x >> 5), g = blockIdx.x & 31;
    float s  = g_gst[(b * 32 + g) * 2];
    float ss = g_gst[(b * 32 + g) * 2 + 1];
    float mean = s * (1.f / 16384.f);
    float rstd = rsqrtf(ss * (1.f / 16384.f) - mean * mean + 1e-5f);
    const float4* p = (const float4*)(g_h0 + (long)b * HW * INNER + g * 16);
    __half* q = g_hnh + (long)b * HW * INNER + g * 16;
    for (int i = threadIdx.x; i < HW * 4; i += 256) {
        int n = i >> 2, j = i & 3;
        int c = g * 16 + j * 4;
        float4 v = p[n * 128 + j];
        __half2 h0 = __floats2half2_rn(
            (v.x - mean) * rstd * gg[c] + gb[c],
            (v.y - mean) * rstd * gg[c + 1] + gb[c + 1]);
        __half2 h1 = __floats2half2_rn(
            (v.z - mean) * rstd * gg[c + 2] + gb[c + 2],
            (v.w - mean) * rstd * gg[c + 3] + gb[c + 3]);
        *(uint2*)(q + n * INNER + j * 4) = make_uint2(
            *(uint32_t*)&h0, *(uint32_t*)&h1);
    }
}

// ===================== fused cross-attention (half2 math) ====================
__global__ void __launch_bounds__(256) ca_attn_k(int b0) {
    __shared__ __half2 Ks[CTXN][DH / 2];
    __shared__ __half2 Vs[CTXN][DH / 2];
    int b = b0 + (blockIdx.x >> 3), h = blockIdx.x & 7;
    const float2* kp = (const float2*)(g_kvc + (long)b * CTXN * 1024 + h * DH);
    const float2* vp = (const float2*)(g_kvc + (long)b * CTXN * 1024 + 512 + h * DH);
    for (int i = threadIdx.x; i < CTXN * 32; i += 256) {
        int j = i >> 5, d = i & 31;
        float2 kf = kp[j * 512 + d];
        float2 vf = vp[j * 512 + d];
        Ks[j][d] = __floats2half2_rn(kf.x, kf.y);
        Vs[j][d] = __floats2half2_rn(vf.x, vf.y);
    }
    __syncthreads();
    int i = blockIdx.y * 256 + threadIdx.x;
    const __half2* qp = (const __half2*)(g_qh + ((long)(b * HW + i)) * INNER + h * DH);
    __half2 qv[32];
    uint4* qv4 = (uint4*)qv;
#pragma unroll
    for (int d = 0; d < 8; d++) qv4[d] = ((const uint4*)qp)[d];

    float l = 0.f;
    __half2 acc[32];
    const __half2 z2 = __float2half2_rn(0.f);
#pragma unroll
    for (int d = 0; d < 32; d++) acc[d] = z2;
    for (int j = 0; j < CTXN; j++) {
        __half2 d2 = __hmul2(qv[0], Ks[j][0]);
#pragma unroll
        for (int d = 1; d < 32; d++) d2 = __hfma2(qv[d], Ks[j][d], d2);
        float s = (__low2float(d2) + __high2float(d2)) * 0.125f;
        float e = __expf(s);
        l += e;
        __half2 e2 = __float2half2_rn(e);
#pragma unroll
        for (int d = 0; d < 32; d++) acc[d] = __hfma2(e2, Vs[j][d], acc[d]);
    }
    float inv = 1.f / l;
    __half* op = g_ofh + ((long)(b * HW + i)) * INNER + h * DH;
#pragma unroll
    for (int d = 0; d < 32; d += 4) {
        __half2 pk[4];
#pragma unroll
        for (int e = 0; e < 4; e++) {
            float2 a = __half22float2(acc[d + e]);
            pk[e] = __floats2half2_rn(a.x * inv, a.y * inv);
        }
        *(uint4*)(op + d * 2) = *(uint4*)pk;
    }
}

// ===================== fp16 mma.sync GEMM (template modes) ===================
// MODE 0: C row-major (stride ldc); optional rsum/rdiv (fused softmax), bias, R.
// MODE 1: C transposed [N, M] per batch (staged, coalesced), Cf/Cb.
// MODE 2: merged qkv — bn<1024: Cb row-major (ldc=1024); bn>=1024: v^T into
//         Cb2 (per-batch 512x1024), staged transpose.
// MODE 3: MODE 0 + GN2 group stats via warp-reduced atomics (contention-free).
// CTA 128x128, 8 warps (2x4, 64x32), BK=64, 3 stages x 32KB, 2 CTAs/SM.
#define STAGE_B 32768
#define GSMEM   98304

__device__ __forceinline__ void frag_load(
    uint32_t aT, uint32_t bT, int wm, int wn, int lane, int kk,
    uint32_t af[4][4], uint32_t bfr[2][4]) {
    const int r0 = lane & 15;
    const int uu = kk * 2 + (lane >> 4);
#pragma unroll
    for (int mi = 0; mi < 4; mi++) {
        int r = wm + mi * 16 + r0;
        ldsm_x4(af[mi], aT + r * 128 + ((uu ^ (r & 7)) << 4));
    }
#pragma unroll
    for (int p = 0; p < 2; p++) {
        int r = wn + p * 16 + r0;
        ldsm_x4(bfr[p], bT + r * 128 + ((uu ^ (r & 7)) << 4));
    }
}

template <int MODE>
__global__ void __launch_bounds__(256, 2) gemm_mma(
    const __half* __restrict__ A_, long sA, int lda,
    const __half* __restrict__ B_, long sB, int ldb,
    float* __restrict__ Cf, __half* __restrict__ Cb, __half* __restrict__ Cb2,
    const float* __restrict__ bias, const float* __restrict__ R,
    float rcoef, float alpha, int M, int N, int K, int ldc,
    float* __restrict__ rsum, const float* __restrict__ rdiv,
    float* __restrict__ gstats) {
    extern __shared__ __align__(128) char sm[];
    const uint32_t sb = smem_to_u32(sm);
    const int tid  = threadIdx.x;
    const int lane = tid & 31;
    const int wid  = tid >> 5;
    const int bz = blockIdx.z;
    const int bm = blockIdx.y * 128;
    const int bn = blockIdx.x * 128;
    const int wm = (wid >> 2) * 64;
    const int wn = (wid & 3) * 32;
    const __half* Ab = A_ + (long)bz * sA;
    const __half* Bb = B_ + (long)bz * sB;

    float acc[4][4][4];
#pragma unroll
    for (int i = 0; i < 4; i++)
#pragma unroll
        for (int j = 0; j < 4; j++)
#pragma unroll
            for (int e = 0; e < 4; e++) acc[i][j][e] = 0.f;

    const int lrow = tid >> 1;
    const int lu0  = (tid & 1) * 4;
    const bool aValid = (bm + lrow) < M;
    const long aOff = aValid ? (long)(bm + lrow) * lda : 0;
    const long bOff = (long)(bn + lrow) * ldb;
    const int nIter = K >> 6;

#define LOADC(i, s) do {                                                        \
    uint32_t dA = sb + (s) * STAGE_B + lrow * 128;                              \
    uint32_t dB = dA + 16384;                                                   \
    const __half* gA = Ab + aOff + ((long)(i) << 6);                            \
    const __half* gB = Bb + bOff + ((long)(i) << 6);                            \
    _Pragma("unroll")                                                           \
    for (int j = 0; j < 4; j++) {                                               \
        int u = lu0 + j;                                                        \
        uint32_t so = (uint32_t)((u ^ (lrow & 7)) << 4);                        \
        cp16(dA + so, gA + u * 8, aValid);                                      \
        cp16(dB + so, gB + u * 8, true);                                        \
    }                                                                           \
} while (0)

    LOADC(0, 0); CP_COMMIT();
    if (1 < nIter) { LOADC(1, 1); }
    CP_COMMIT();

    uint32_t af[4][4], bfr[2][4];

    for (int it = 0; it < nIter; it++) {
        const int s = it % 3;
        if (it + 1 < nIter) cp_wait<1>(); else cp_wait<0>();
        __syncthreads();
        if (it + 2 < nIter) { LOADC(it + 2, (it + 2) % 3); CP_COMMIT(); }

        const uint32_t aT = sb + s * STAGE_B;
        const uint32_t bT = aT + 16384;
#pragma unroll
        for (int kk = 0; kk < 4; kk++) {
            frag_load(aT, bT, wm, wn, lane, kk, af, bfr);
#pragma unroll
            for (int mi = 0; mi < 4; mi++)
#pragma unroll
                for (int p = 0; p < 2; p++) {
                    mma_f16(acc[mi][2 * p],     af[mi], bfr[p][0], bfr[p][2]);
                    mma_f16(acc[mi][2 * p + 1], af[mi], bfr[p][1], bfr[p][3]);
                }
        }
        __syncthreads();
    }

    // ------------------------------ epilogue ------------------------------
    const int tr = lane >> 2;
    const int tc = (lane & 3) * 2;
    const bool staged = (MODE == 1) || (MODE == 2 && bn >= 1024);
    if (staged) {
        float* st = (float*)sm;
#pragma unroll
        for (int mi = 0; mi < 4; mi++)
#pragma unroll
            for (int r2 = 0; r2 < 2; r2++) {
                const int ml = wm + mi * 16 + tr + r2 * 8;
#pragma unroll
                for (int nj = 0; nj < 4; nj++) {
                    const int nl = wn + nj * 8 + tc;
                    st[nl * 132 + ml]       = acc[mi][nj][r2 * 2 + 0] * alpha;
                    st[(nl + 1) * 132 + ml] = acc[mi][nj][r2 * 2 + 1] * alpha;
                }
            }
        __syncthreads();
        if (MODE == 1) {
            const long bzMN = (long)bz * M * N;
#pragma unroll
            for (int r = 0; r < 16; r++) {
                const int nl = wid * 16 + r;
                const int n = bn + nl;
                float bv = bias ? bias[n] : 0.f;
                float4 v = *(float4*)&st[nl * 132 + lane * 4];
                v.x += bv; v.y += bv; v.z += bv; v.w += bv;
                const long i0 = bzMN + (long)n * M + bm + lane * 4;
                if (R) {
                    float4 rv = *(const float4*)(R + i0);
                    v.x += rcoef * rv.x; v.y += rcoef * rv.y;
                    v.z += rcoef * rv.z; v.w += rcoef * rv.w;
                }
                if (Cf) *(float4*)(Cf + i0) = v;
                if (Cb) {
                    __half2 h0v = __floats2half2_rn(v.x, v.y);
                    __half2 h1v = __floats2half2_rn(v.z, v.w);
                    *(uint2*)(Cb + i0) = make_uint2(*(uint32_t*)&h0v, *(uint32_t*)&h1v);
                }
            }
        } else {
#pragma unroll
            for (int r = 0; r < 16; r++) {
                const int nl = wid * 16 + r;
                const int vrow = bn - 1024 + nl;
                float4 v = *(float4*)&st[nl * 132 + lane * 4];
                __half2 h0v = __floats2half2_rn(v.x, v.y);
                __half2 h1v = __floats2half2_rn(v.z, v.w);
                const long i0 = (long)bz * 524288 + (long)vrow * 1024 + bm + lane * 4;
                *(uint2*)(Cb2 + i0) = make_uint2(*(uint32_t*)&h0v, *(uint32_t*)&h1v);
            }
        }
    } else {
        const long bzC = (long)bz * M * ldc;
        float gs0 = 0.f, gss0 = 0.f, gs1 = 0.f, gss1 = 0.f;
#pragma unroll
        for (int mi = 0; mi < 4; mi++) {
#pragma unroll
            for (int r2 = 0; r2 < 2; r2++) {
                const int m = bm + wm + mi * 16 + tr + r2 * 8;
                if (m >= M) continue;
                float rAcc = 0.f;
                float inv = 1.f;
                if (rdiv) inv = 1.f / rdiv[(long)bz * M + m];
#pragma unroll
                for (int nj = 0; nj < 4; nj++) {
                    const int n = bn + wn + nj * 8 + tc;
                    float v0 = acc[mi][nj][r2 * 2 + 0] * alpha;
                    float v1 = acc[mi][nj][r2 * 2 + 1] * alpha;
                    if (bias) { v0 += bias[n]; v1 += bias[n + 1]; }
                    if (rsum) {
                        v0 = __expf(v0); v1 = __expf(v1);
                        rAcc += v0 + v1;
                    }
                    v0 *= inv; v1 *= inv;
                    const long i0 = bzC + (long)m * ldc + n;
                    if (R) {
                        float2 rv = *(const float2*)(R + i0);
                        v0 += rcoef * rv.x; v1 += rcoef * rv.y;
                    }
                    if (MODE == 3) {
                        if (nj < 2) { gs0 += v0 + v1; gss0 += v0 * v0 + v1 * v1; }
                        else        { gs1 += v0 + v1; gss1 += v0 * v0 + v1 * v1; }
                    }
                    if (Cf) *(float2*)(Cf + i0) = make_float2(v0, v1);
                    if (Cb) {
                        __half2 hv = __floats2half2_rn(v0, v1);
                        *(uint32_t*)(Cb + i0) = *(uint32_t*)&hv;
                    }
                }
                if (rsum) {
                    rAcc += __shfl_xor_sync(0xffffffffu, rAcc, 1);
                    rAcc += __shfl_xor_sync(0xffffffffu, rAcc, 2);
                    if ((lane & 3) == 0)
                        atomicAdd(&rsum[(long)bz * M + m], rAcc);
                }
            }
        }
        if (MODE == 3) {
            gs0  = warpSum(gs0);  gss0 = warpSum(gss0);
            gs1  = warpSum(gs1);  gss1 = warpSum(gss1);
            if (lane == 0) {
                const int g0 = (bn + wn) >> 4;
                atomicAdd(&gstats[((long)bz * 32 + g0) * 2],     gs0);
                atomicAdd(&gstats[((long)bz * 32 + g0) * 2 + 1], gss0);
                atomicAdd(&gstats[((long)bz * 32 + g0 + 1) * 2],     gs1);
                atomicAdd(&gstats[((long)bz * 32 + g0 + 1) * 2 + 1], gss1);
            }
        }
    }
#undef LOADC
}

template <int MODE>
static void gemm(cudaStream_t st, int nb,
                 const __half* A, long sA, int lda,
                 const __half* B, long sB, int ldb,
                 float* Cf, __half* Cb, __half* Cb2,
                 const float* bias, const float* R,
                 float rcoef, float alpha, int M, int N, int K, int ldc,
                 float* rsum, const float* rdiv, float* gstats) {
    cudaFuncSetAttribute(gemm_mma<MODE>, cudaFuncAttributeMaxDynamicSharedMemorySize, GSMEM);
    dim3 grid(N / 128, (M + 127) / 128, nb);
    gemm_mma<MODE><<<grid, 256, GSMEM, st>>>(A, sA, lda, B, sB, ldb, Cf, Cb, Cb2,
                                             bias, R, rcoef, alpha, M, N, K, ldc,
                                             rsum, rdiv, gstats);
}

// ===================== per-chain launch bundle ===============================
struct Bufs {
    const float *x, *gn1_g, *gn1_b, *b_in, *sa_gng, *sa_gnb, *ca_bo, *b_out;
    float *h0, *h1, *kvc, *rs, *gst, *out;
    __half *wh_in, *wh_qkv, *wh_sap, *wh_caq, *wh_cao, *wh_out;
    __half *xnh, *hnh, *qkh, *qh, *vth, *oh, *h1h, *h2h, *ofh, *attnh;
};

static void run_chain(cudaStream_t st, int b0, const Bufs& B,
                      cudaEvent_t evCvt, cudaEvent_t evKV) {
    const float inv_sqrt_c = 0.044194173824159216f;   // 512^-0.5
    // batch-offset bases
    const float*  x    = B.x    + (long)b0 * CIN * HW;
    float*  h0   = B.h0   + (long)b0 * HW * INNER;
    float*  h1   = B.h1   + (long)b0 * HW * INNER;
    float*  rs   = B.rs   + (long)b0 * HW;
    float*  gst  = B.gst  + (long)b0 * 64;
    float*  out  = B.out  + (long)b0 * CIN * HW;
    __half* xnh  = B.xnh  + (long)b0 * HW * CIN;
    __half* hnh  = B.hnh  + (long)b0 * HW * INNER;
    __half* qkh  = B.qkh  + (long)b0 * HW * 1024;
    __half* qh   = B.qh   + (long)b0 * HW * INNER;
    __half* vth  = B.vth  + (long)b0 * HW * INNER;
    __half* oh   = B.oh   + (long)b0 * HW * INNER;
    __half* h1h  = B.h1h  + (long)b0 * HW * INNER;
    __half* h2h  = B.h2h  + (long)b0 * HW * INNER;
    __half* ofh  = B.ofh  + (long)b0 * HW * INNER;
    __half* attnh= B.attnh+ (long)b0 * HW * HW;

    gn1_stats_k<<<NBH * 32, 256, 0, st>>>(B.x, b0);
    gn1_apply_k<<<dim3(32, 8, NBH), dim3(32, 8), 0, st>>>(B.x, B.gn1_g, B.gn1_b, b0);
    cudaStreamWaitEvent(st, evCvt, 0);
    gemm<3>(st, NBH, xnh, (long)HW * CIN, CIN, B.wh_in, 0, CIN, h0, nullptr, nullptr,
            B.b_in, nullptr, 0.f, 1.f, HW, INNER, CIN, INNER, nullptr, nullptr, gst);
    gn2_apply_k<<<NBH * 32, 256, 0, st>>>(B.sa_gng, B.sa_gnb, b0);
    gemm<2>(st, NBH, hnh, (long)HW * INNER, INNER, B.wh_qkv, 0, INNER, nullptr, qkh, vth,
            nullptr, nullptr, 0.f, 1.f, HW, 1536, INNER, 1024, nullptr, nullptr, nullptr);
    gemm<0>(st, NBH, qkh, (long)HW * 1024, 1024, qkh + 512, (long)HW * 1024, 1024,
            nullptr, attnh, nullptr, nullptr, nullptr, 0.f, inv_sqrt_c,
            HW, HW, INNER, HW, rs, nullptr, nullptr);
    gemm<0>(st, NBH, attnh, (long)HW * HW, HW, vth, (long)INNER * HW, HW,
            nullptr, oh, nullptr, nullptr, nullptr, 0.f, 1.f,
            HW, INNER, HW, INNER, nullptr, rs, nullptr);
    gemm<0>(st, NBH, oh, (long)HW * INNER, INNER, B.wh_sap, 0, INNER, h1, h1h, nullptr,
            nullptr, h0, 2.f, 1.f, HW, INNER, INNER, INNER, nullptr, nullptr, nullptr);
    gemm<0>(st, NBH, h1h, (long)HW * INNER, INNER, B.wh_caq, 0, INNER, nullptr, qh, nullptr,
            nullptr, nullptr, 0.f, 1.f, HW, INNER, INNER, INNER, nullptr, nullptr, nullptr);
    cudaStreamWaitEvent(st, evKV, 0);
    ca_attn_k<<<dim3(NBH * 8, 4), 256, 0, st>>>(b0);
    gemm<0>(st, NBH, ofh, (long)HW * INNER, INNER, B.wh_cao, 0, INNER, nullptr, h2h, nullptr,
            B.ca_bo, h1, 1.f, 1.f, HW, INNER, INNER, INNER, nullptr, nullptr, nullptr);
    gemm<1>(st, NBH, h2h, (long)HW * INNER, INNER, B.wh_out, 0, INNER, out, nullptr, nullptr,
            B.b_out, x, 1.f, 1.f, HW, CIN, INNER, CIN, nullptr, nullptr, nullptr);
}

// ===================== driver ================================================
extern "C" void kernel_launch(void* const* d_in, const int* in_sizes, int n_in,
                              void* d_out, int out_size) {
    const float* x      = (const float*)d_in[0];
    const float* ctx    = (const float*)d_in[1];
    const float* gn1_g  = (const float*)d_in[2];
    const float* gn1_b  = (const float*)d_in[3];
    const float* w_in   = (const float*)d_in[4];
    const float* b_in   = (const float*)d_in[5];
    const float* sa_wk  = (const float*)d_in[6];
    const float* sa_wq  = (const float*)d_in[7];
    const float* sa_wv  = (const float*)d_in[8];
    const float* sa_wp  = (const float*)d_in[9];
    const float* sa_gng = (const float*)d_in[10];
    const float* sa_gnb = (const float*)d_in[11];
    const float* ca_wq  = (const float*)d_in[12];
    const float* ca_wk  = (const float*)d_in[13];
    const float* ca_wv  = (const float*)d_in[14];
    const float* ca_wo  = (const float*)d_in[15];
    const float* ca_bo  = (const float*)d_in[16];
    const float* w_out  = (const float*)d_in[17];
    const float* b_out  = (const float*)d_in[18];
    float* out = (float*)d_out;

    static cudaStream_t s_side = nullptr, s_b = nullptr;
    static cudaEvent_t  s_evFork = nullptr, s_evCvt = nullptr, s_evKV = nullptr,
                        s_evB = nullptr;
    if (!s_side) {
        cudaStreamCreateWithFlags(&s_side, cudaStreamNonBlocking);
        cudaStreamCreateWithFlags(&s_b,    cudaStreamNonBlocking);
        cudaEventCreateWithFlags(&s_evFork, cudaEventDisableTiming);
        cudaEventCreateWithFlags(&s_evCvt,  cudaEventDisableTiming);
        cudaEventCreateWithFlags(&s_evKV,   cudaEventDisableTiming);
        cudaEventCreateWithFlags(&s_evB,    cudaEventDisableTiming);
    }
    cudaStream_t mainS = 0;

    Bufs B;
    B.x = x; B.gn1_g = gn1_g; B.gn1_b = gn1_b; B.b_in = b_in;
    B.sa_gng = sa_gng; B.sa_gnb = sa_gnb; B.ca_bo = ca_bo; B.b_out = b_out;
    B.out = out;
    cudaGetSymbolAddress((void**)&B.h0,  g_h0);
    cudaGetSymbolAddress((void**)&B.h1,  g_h1);
    cudaGetSymbolAddress((void**)&B.kvc, g_kvc);
    cudaGetSymbolAddress((void**)&B.rs,  g_rsum);
    cudaGetSymbolAddress((void**)&B.gst, g_gst);
    __half* wh;
    cudaGetSymbolAddress((void**)&wh, g_wh);
    cudaGetSymbolAddress((void**)&B.xnh, g_xnh);
    cudaGetSymbolAddress((void**)&B.hnh, g_hnh);
    cudaGetSymbolAddress((void**)&B.qkh, g_qkh);
    cudaGetSymbolAddress((void**)&B.qh,  g_qh);
    cudaGetSymbolAddress((void**)&B.vth, g_vth);
    cudaGetSymbolAddress((void**)&B.oh,  g_oh);
    cudaGetSymbolAddress((void**)&B.h1h, g_h1h);
    cudaGetSymbolAddress((void**)&B.h2h, g_h2h);
    cudaGetSymbolAddress((void**)&B.ofh, g_ofh);
    cudaGetSymbolAddress((void**)&B.attnh, g_attn);
    B.wh_in  = wh;
    B.wh_qkv = wh + 131072;
    B.wh_sap = wh + 917504;
    B.wh_caq = wh + 1179648;
    __half* wh_cakv = wh + 1441792;
    B.wh_cao = wh + 2228224;
    B.wh_out = wh + 2490368;
    __half* ctx_h = wh + 2621440;

    CvtSrc cs;
    cs.p[0] = w_in;  cs.p[1] = sa_wq; cs.p[2] = sa_wk; cs.p[3] = sa_wv;
    cs.p[4] = sa_wp; cs.p[5] = ca_wq; cs.p[6] = ca_wk; cs.p[7] = ca_wv;
    cs.p[8] = ca_wo; cs.p[9] = w_out; cs.p[10] = ctx;

    // ---- fork: side (cvt -> cakv) and chain B off the capture stream ----
    cudaEventRecord(s_evFork, mainS);
    cudaStreamWaitEvent(s_side, s_evFork, 0);
    cudaStreamWaitEvent(s_b,    s_evFork, 0);

    cvt_k<<<(int)((WH_TOTAL + 255) / 256), 256, 0, s_side>>>(cs);
    cudaEventRecord(s_evCvt, s_side);
    gemm<0>(s_side, NB, ctx_h, (long)CTXN * CTXD, CTXD, wh_cakv, 0, CTXD,
            B.kvc, nullptr, nullptr, nullptr, nullptr, 0.f, 1.f,
            CTXN, 1024, CTXD, 1024, nullptr, nullptr, nullptr);
    cudaEventRecord(s_evKV, s_side);

    // chain A: batches 0-7 on main; chain B: batches 8-15 on s_b
    run_chain(mainS, 0,   B, s_evCvt, s_evKV);
    run_chain(s_b,   NBH, B, s_evCvt, s_evKV);

    // join chain B back into the capture origin stream
    cudaEventRecord(s_evB, s_b);
    cudaStreamWaitEvent(mainS, s_evB, 0);
}